// round 1
// baseline (speedup 1.0000x reference)
#include <cuda_runtime.h>

// ============================================================================
// MultiHeadAttention fused block, fp32 baseline.
// B=8, S=1024, D=512, H=8, DH=1024.
// Stages:
//   0. detect mask dtype (uint8 / int32 / float32)
//   1. q = Q@Wq+bq ; k = K@Wk+bk ; v = V@Wv+bv         (NN SGEMM, M=N=8192,K=512)
//   2. scores[b,h] = q[b,:,h,:] @ k[b,:,h,:]^T          (NT batched SGEMM, 64x)
//   3. softmax(scale + mask) in-place on scores
//   4. ctx[b,:,h,:] = attn[b,h] @ v[b,:,h,:]            (NN batched SGEMM, 64x)
//   5. o = ctx @ Wo + bo + Q                            (NN SGEMM + residual)
//   6. out = LayerNorm(o) * gamma + beta
// All shapes divide the 128x128x8 tiles exactly -> no bounds checks.
// ============================================================================

#define BM 128
#define BN 128
#define BK 8
#define TM 8
#define TN 8

// ---- scratch (static device globals: the sanctioned alloc-free path) ----
__device__ __align__(256) float g_q[(size_t)8192 * 8192];   // 256 MB
__device__ __align__(256) float g_k[(size_t)8192 * 8192];   // 256 MB
__device__ __align__(256) float g_v[(size_t)8192 * 8192];   // 256 MB
__device__ __align__(256) float g_s[(size_t)64 * 1024 * 1024]; // scores/attn, 256 MB
__device__ __align__(256) float g_c[(size_t)8192 * 8192];   // ctx, 256 MB
__device__ __align__(256) float g_o[(size_t)8192 * 512];    // pre-LN out, 16 MB
__device__ int g_mask_mode;  // 0 = uint8, 1 = int32, 2 = float32

// ============================================================================
// Mask dtype detection: scan first 4096 uint32 words (16 KB, safe for all
// encodings since mask has >= 8.4M bytes).
//   float32 bool: words in {0x00000000, 0x3F800000}
//   int32   bool: words in {0, 1}
//   uint8   bool: packed 0/1 bytes -> words > 1 occur w.p. ~1 for p=0.15
// ============================================================================
__global__ void detect_mask_kernel(const unsigned int* __restrict__ m) {
    __shared__ int sawFloat, sawByte;
    if (threadIdx.x == 0) { sawFloat = 0; sawByte = 0; }
    __syncthreads();
    for (int i = threadIdx.x; i < 4096; i += 256) {
        unsigned int w = m[i];
        if (w == 0x3F800000u) sawFloat = 1;
        else if (w > 1u) sawByte = 1;
    }
    __syncthreads();
    if (threadIdx.x == 0)
        g_mask_mode = sawFloat ? 2 : (sawByte ? 0 : 1);
}

// ============================================================================
// Generic SGEMM: C = A @ op(B) (+bias) (+residual)
//   A is [M,K] row-major (K contiguous), stride lda.
//   B_KMAJOR=false: B[k,n] at B + k*ldb + n        (NN)
//   B_KMAJOR=true : B[n,k] at B + n*ldb + k        (NT, i.e. C = A @ B^T)
// Batched over blockIdx.z: offset = (z/HD)*O1 + (z%HD)*O2 per operand.
// 128x128 tile, BK=8, 256 threads, 8x8 per thread, smem double-buffered.
// Requires M%128==0, N%128==0, K%8==0 (true for every call here).
// ============================================================================
template <bool B_KMAJOR>
__global__ void __launch_bounds__(256)
gemm_kernel(const float* __restrict__ A, const float* __restrict__ B,
            const float* __restrict__ bias, const float* __restrict__ res,
            float* __restrict__ C,
            int M, int N, int K, int lda, int ldb, int ldc,
            long aO1, long aO2, long bO1, long bO2, long cO1, long cO2, int HD)
{
    const int z  = blockIdx.z;
    const int zb = z / HD, zh = z % HD;
    A += (long)zb * aO1 + (long)zh * aO2;
    B += (long)zb * bO1 + (long)zh * bO2;
    C += (long)zb * cO1 + (long)zh * cO2;
    if (res) res += (long)zb * cO1 + (long)zh * cO2;

    __shared__ __align__(16) float As[2][BK][BM];
    __shared__ __align__(16) float Bs[2][BK][BN];

    const int tid  = threadIdx.x;
    const int row0 = blockIdx.y * BM;
    const int col0 = blockIdx.x * BN;

    // A tile load map: 128x8 elems, one float4 per thread
    const int am = tid >> 1;
    const int ak = (tid & 1) << 2;
    // B tile load map (NN): 8x128, one float4 per thread
    const int bkn = tid >> 5;
    const int bnn = (tid & 31) << 2;
    // B tile load map (NT): 128 (n) x 8 (k), one float4 per thread
    const int bnt = tid >> 1;
    const int bkt = (tid & 1) << 2;

    const int tx = tid & 15;   // 16 col-groups
    const int ty = tid >> 4;   // 16 row-groups

    float acc[TM][TN];
#pragma unroll
    for (int i = 0; i < TM; i++)
#pragma unroll
        for (int j = 0; j < TN; j++) acc[i][j] = 0.f;

    // ---- prologue: load tile 0 into buffer 0 ----
    {
        float4 va = *(const float4*)(A + (long)(row0 + am) * lda + ak);
        As[0][ak + 0][am] = va.x; As[0][ak + 1][am] = va.y;
        As[0][ak + 2][am] = va.z; As[0][ak + 3][am] = va.w;
        if (B_KMAJOR) {
            float4 vb = *(const float4*)(B + (long)(col0 + bnt) * ldb + bkt);
            Bs[0][bkt + 0][bnt] = vb.x; Bs[0][bkt + 1][bnt] = vb.y;
            Bs[0][bkt + 2][bnt] = vb.z; Bs[0][bkt + 3][bnt] = vb.w;
        } else {
            float4 vb = *(const float4*)(B + (long)bkn * ldb + col0 + bnn);
            *(float4*)&Bs[0][bkn][bnn] = vb;
        }
    }
    __syncthreads();

    int buf = 0;
    for (int kt = 0; kt < K; kt += BK) {
        const int nxt = buf ^ 1;
        if (kt + BK < K) {
            float4 va = *(const float4*)(A + (long)(row0 + am) * lda + (kt + BK) + ak);
            As[nxt][ak + 0][am] = va.x; As[nxt][ak + 1][am] = va.y;
            As[nxt][ak + 2][am] = va.z; As[nxt][ak + 3][am] = va.w;
            if (B_KMAJOR) {
                float4 vb = *(const float4*)(B + (long)(col0 + bnt) * ldb + (kt + BK) + bkt);
                Bs[nxt][bkt + 0][bnt] = vb.x; Bs[nxt][bkt + 1][bnt] = vb.y;
                Bs[nxt][bkt + 2][bnt] = vb.z; Bs[nxt][bkt + 3][bnt] = vb.w;
            } else {
                float4 vb = *(const float4*)(B + (long)(kt + BK + bkn) * ldb + col0 + bnn);
                *(float4*)&Bs[nxt][bkn][bnn] = vb;
            }
        }
#pragma unroll
        for (int kk = 0; kk < BK; kk++) {
            float4 a0 = *(const float4*)&As[buf][kk][ty * TM];
            float4 a1 = *(const float4*)&As[buf][kk][ty * TM + 4];
            float4 b0 = *(const float4*)&Bs[buf][kk][tx * TN];
            float4 b1 = *(const float4*)&Bs[buf][kk][tx * TN + 4];
            float ar[8] = {a0.x, a0.y, a0.z, a0.w, a1.x, a1.y, a1.z, a1.w};
            float br[8] = {b0.x, b0.y, b0.z, b0.w, b1.x, b1.y, b1.z, b1.w};
#pragma unroll
            for (int i = 0; i < TM; i++)
#pragma unroll
                for (int j = 0; j < TN; j++)
                    acc[i][j] += ar[i] * br[j];
        }
        __syncthreads();
        buf = nxt;
    }

    // ---- epilogue ----
#pragma unroll
    for (int i = 0; i < TM; i++) {
        const int r = row0 + ty * TM + i;
        const int c = col0 + tx * TN;
        float vals[8];
#pragma unroll
        for (int j = 0; j < TN; j++) vals[j] = acc[i][j];
        if (bias) {
#pragma unroll
            for (int j = 0; j < TN; j++) vals[j] += bias[c + j];
        }
        if (res) {
            float4 r0 = *(const float4*)(res + (long)r * ldc + c);
            float4 r1 = *(const float4*)(res + (long)r * ldc + c + 4);
            vals[0] += r0.x; vals[1] += r0.y; vals[2] += r0.z; vals[3] += r0.w;
            vals[4] += r1.x; vals[5] += r1.y; vals[6] += r1.z; vals[7] += r1.w;
        }
        float4 o0 = {vals[0], vals[1], vals[2], vals[3]};
        float4 o1 = {vals[4], vals[5], vals[6], vals[7]};
        *(float4*)(C + (long)r * ldc + c)     = o0;
        *(float4*)(C + (long)r * ldc + c + 4) = o1;
    }
}

// ============================================================================
// Fused scale + mask + softmax, in-place over one score row of length S=1024.
// grid = (S, B*H), 256 threads, 4 elements/thread.
// Matches reference: s = score/32 ; if mask -> -1e9 ; softmax.
// ============================================================================
__global__ void __launch_bounds__(256)
softmax_kernel(float* __restrict__ attn, const void* __restrict__ mask,
               int S, int H, float scale)
{
    const int i = blockIdx.x;
    const int z = blockIdx.y;
    const int b = z / H;
    float* p = attn + ((long)z * S + (long)i) * S;
    const long mbase = (long)b * S * S + (long)i * S;
    const int tid = threadIdx.x;
    const int mode = g_mask_mode;

    float v[4];
    float mx = -3.4e38f;
#pragma unroll
    for (int r = 0; r < 4; r++) {
        const int j = tid + r * 256;
        float s = p[j] * scale;
        bool m;
        if (mode == 0)      m = ((const unsigned char*)mask)[mbase + j] != 0;
        else if (mode == 1) m = ((const int*)mask)[mbase + j] != 0;
        else                m = ((const float*)mask)[mbase + j] != 0.f;
        if (m) s = -1e9f;
        v[r] = s;
        mx = fmaxf(mx, s);
    }

    __shared__ float red[256];
    red[tid] = mx;
    __syncthreads();
    for (int st = 128; st > 0; st >>= 1) {
        if (tid < st) red[tid] = fmaxf(red[tid], red[tid + st]);
        __syncthreads();
    }
    mx = red[0];
    __syncthreads();

    float sum = 0.f;
#pragma unroll
    for (int r = 0; r < 4; r++) {
        v[r] = __expf(v[r] - mx);
        sum += v[r];
    }
    red[tid] = sum;
    __syncthreads();
    for (int st = 128; st > 0; st >>= 1) {
        if (tid < st) red[tid] += red[tid + st];
        __syncthreads();
    }
    const float inv = 1.f / red[0];
#pragma unroll
    for (int r = 0; r < 4; r++)
        p[tid + r * 256] = v[r] * inv;
}

// ============================================================================
// LayerNorm over D=512, one block (256 threads) per row.
// ============================================================================
__global__ void __launch_bounds__(256)
layernorm_kernel(const float* __restrict__ x, const float* __restrict__ gamma,
                 const float* __restrict__ beta, float* __restrict__ out, int D)
{
    const int row = blockIdx.x;
    const float* p = x + (long)row * D;
    const int tid = threadIdx.x;

    const float a0 = p[tid];
    const float a1 = p[tid + 256];

    __shared__ float red[256];
    red[tid] = a0 + a1;
    __syncthreads();
    for (int st = 128; st > 0; st >>= 1) {
        if (tid < st) red[tid] += red[tid + st];
        __syncthreads();
    }
    const float mean = red[0] / (float)D;
    __syncthreads();

    const float d0 = a0 - mean, d1 = a1 - mean;
    red[tid] = d0 * d0 + d1 * d1;
    __syncthreads();
    for (int st = 128; st > 0; st >>= 1) {
        if (tid < st) red[tid] += red[tid + st];
        __syncthreads();
    }
    const float rstd = rsqrtf(red[0] / (float)D + 1e-5f);

    out[(long)row * D + tid]       = d0 * rstd * gamma[tid] + beta[tid];
    out[(long)row * D + tid + 256] = d1 * rstd * gamma[tid + 256] + beta[tid + 256];
}

// ============================================================================
// Launch
// ============================================================================
extern "C" void kernel_launch(void* const* d_in, const int* in_sizes, int n_in,
                              void* d_out, int out_size)
{
    const float* Q     = (const float*)d_in[0];
    const float* Kin   = (const float*)d_in[1];
    const float* Vin   = (const float*)d_in[2];
    const void*  Mask  = d_in[3];
    const float* Wq    = (const float*)d_in[4];
    const float* bq    = (const float*)d_in[5];
    const float* Wk    = (const float*)d_in[6];
    const float* bk    = (const float*)d_in[7];
    const float* Wv    = (const float*)d_in[8];
    const float* bv    = (const float*)d_in[9];
    const float* Wo    = (const float*)d_in[10];
    const float* bo    = (const float*)d_in[11];
    const float* gamma = (const float*)d_in[12];
    const float* beta  = (const float*)d_in[13];
    float* out = (float*)d_out;

    float *q, *k, *v, *s, *c, *o;
    cudaGetSymbolAddress((void**)&q, g_q);
    cudaGetSymbolAddress((void**)&k, g_k);
    cudaGetSymbolAddress((void**)&v, g_v);
    cudaGetSymbolAddress((void**)&s, g_s);
    cudaGetSymbolAddress((void**)&c, g_c);
    cudaGetSymbolAddress((void**)&o, g_o);

    const int S = 1024, H = 8, D = 512, NH = 8192; // NH = H*DH = rows/cols of big GEMMs
    const long SS = (long)S * S;
    dim3 blk(256);

    // 0. mask dtype detection
    detect_mask_kernel<<<1, 256>>>((const unsigned int*)Mask);

    // 1. QKV projections: [8192,512] @ [512,8192] + bias
    dim3 gp(NH / BN, 8192 / BM, 1);
    gemm_kernel<false><<<gp, blk>>>(Q,   Wq, bq, nullptr, q, 8192, NH, D, D, NH, NH, 0, 0, 0, 0, 0, 0, 1);
    gemm_kernel<false><<<gp, blk>>>(Kin, Wk, bk, nullptr, k, 8192, NH, D, D, NH, NH, 0, 0, 0, 0, 0, 0, 1);
    gemm_kernel<false><<<gp, blk>>>(Vin, Wv, bv, nullptr, v, 8192, NH, D, D, NH, NH, 0, 0, 0, 0, 0, 0, 1);

    // 2. scores[b,h] = q_bh [1024,1024] @ k_bh^T  (64 batches)
    dim3 gs(S / BN, S / BM, 64);
    gemm_kernel<true><<<gs, blk>>>(q, k, nullptr, nullptr, s,
                                   S, S, 1024, NH, NH, S,
                                   (long)S * NH, 1024,       // A offsets per (b,h)
                                   (long)S * NH, 1024,       // B offsets
                                   (long)H * SS, SS,         // C offsets
                                   H);

    // 3. scale + mask + softmax in-place (scale = 1/sqrt(1024) = 1/32)
    softmax_kernel<<<dim3(S, 64), blk>>>(s, Mask, S, H, 0.03125f);

    // 4. ctx[b,:,h,:] = attn[b,h] @ v_bh  (64 batches)
    gemm_kernel<false><<<gs, blk>>>(s, v, nullptr, nullptr, c,
                                    S, S, 1024, S, NH, NH,
                                    (long)H * SS, SS,
                                    (long)S * NH, 1024,
                                    (long)S * NH, 1024,
                                    H);

    // 5. out projection + bias + residual: [8192,8192] @ [8192,512] + bo + Q
    dim3 go(D / BN, 8192 / BM, 1);
    gemm_kernel<false><<<go, blk>>>(c, Wo, bo, Q, o, 8192, D, NH, NH, D, D, 0, 0, 0, 0, 0, 0, 1);

    // 6. LayerNorm
    layernorm_kernel<<<8192, blk>>>(o, gamma, beta, out, D);
}

// round 6
// speedup vs baseline: 1.7500x; 1.7500x over previous
#include <cuda_runtime.h>
#include <cstdint>

// ============================================================================
// MultiHeadAttention via sm_100-portable bf16 mma.sync (3-product split GEMM).
// B=8, S=1024, D=512, H=8, DH=1024.
// Harness PTX target is plain sm_100 -> tcgen05 unavailable; use
// ldmatrix + mma.sync.aligned.m16n8k16.row.col.f32.bf16.bf16.f32.
// (Resubmission of the audited round-4/5 kernel: every prior attempt of this
//  exact design died to broker-side "container failed twice", an error class
//  that also hit the EMPTY STUB in round 0 — i.e. it is content-independent.)
//
// All GEMMs canonicalized to NT (A[M,K] K-major, B[N,K] K-major):
//   - Wq/Wk/Wv/Wo transposed once
//   - V projection stores its output transposed (v_t[b, n(h,dh), s])
// fp32 accuracy via 2-way bf16 split: x = hi + lo, C += hh + hl + lh.
// ctx aliases the k-projection buffer (dead after the scores GEMM).
// ============================================================================

#define LDSM_X4(r0, r1, r2, r3, addr) \
    asm volatile("ldmatrix.sync.aligned.m8n8.x4.shared.b16 {%0,%1,%2,%3}, [%4];" \
                 : "=r"(r0), "=r"(r1), "=r"(r2), "=r"(r3) : "r"(addr))

#define MMA_BF16(d, a, b0, b1) \
    asm volatile("mma.sync.aligned.m16n8k16.row.col.f32.bf16.bf16.f32 " \
                 "{%0,%1,%2,%3}, {%4,%5,%6,%7}, {%8,%9}, {%0,%1,%2,%3};" \
                 : "+f"((d)[0]), "+f"((d)[1]), "+f"((d)[2]), "+f"((d)[3]) \
                 : "r"((a)[0]), "r"((a)[1]), "r"((a)[2]), "r"((a)[3]), \
                   "r"(b0), "r"(b1))

__device__ __forceinline__ uint32_t smem_u32(const void* p) {
    uint32_t a;
    asm("{ .reg .u64 t; cvta.to.shared.u64 t, %1; cvt.u32.u64 %0, t; }"
        : "=r"(a) : "l"(p));
    return a;
}

// pack hi parts (top 16 bits) of two floats: {y.hi, x.hi} -> bf16x2 (x low)
__device__ __forceinline__ uint32_t pack_hi(float x, float y) {
    uint32_t r;
    asm("prmt.b32 %0, %1, %2, 0x7632;"
        : "=r"(r) : "r"(__float_as_uint(x)), "r"(__float_as_uint(y)));
    return r;
}
// rn-convert two floats to bf16x2 (x low half)
__device__ __forceinline__ uint32_t pack_rn(float x, float y) {
    uint32_t r;
    asm("cvt.rn.bf16x2.f32 %0, %1, %2;" : "=r"(r) : "f"(y), "f"(x));
    return r;
}

// ---------------- device scratch ----------------
__device__ __align__(256) float g_q  [(size_t)8192 * 8192];      // q proj
__device__ __align__(256) float g_k  [(size_t)8192 * 8192];      // k proj, later ctx
__device__ __align__(256) float g_vt [(size_t)8192 * 8192];      // v^T [b][n(h,dh)][s]
__device__ __align__(256) float g_s  [(size_t)64 * 1024 * 1024]; // scores/attn
__device__ __align__(256) float g_o  [(size_t)8192 * 512];       // pre-LN
__device__ __align__(256) float g_wqt[(size_t)8192 * 512];
__device__ __align__(256) float g_wkt[(size_t)8192 * 512];
__device__ __align__(256) float g_wvt[(size_t)8192 * 512];
__device__ __align__(256) float g_wot[(size_t)512 * 8192];
__device__ int g_mask_mode;

// ---------------- mask dtype detection ----------------
__global__ void detect_mask_kernel(const unsigned int* __restrict__ m) {
    __shared__ int sawFloat, sawByte;
    if (threadIdx.x == 0) { sawFloat = 0; sawByte = 0; }
    __syncthreads();
    for (int i = threadIdx.x; i < 4096; i += 256) {
        unsigned int w = m[i];
        if (w == 0x3F800000u) sawFloat = 1;
        else if (w > 1u) sawByte = 1;
    }
    __syncthreads();
    if (threadIdx.x == 0) g_mask_mode = sawFloat ? 2 : (sawByte ? 0 : 1);
}

// ---------------- transpose [R,C] -> [C,R] ----------------
__global__ void __launch_bounds__(256)
transpose_kernel(const float* __restrict__ in, float* __restrict__ out, int R, int C) {
    __shared__ float t[32][33];
    int x = blockIdx.x * 32 + threadIdx.x;
    int y0 = blockIdx.y * 32;
#pragma unroll
    for (int j = threadIdx.y; j < 32; j += 8)
        t[j][threadIdx.x] = in[(long)(y0 + j) * C + x];
    __syncthreads();
    int xo = blockIdx.y * 32 + threadIdx.x;
    int yo0 = blockIdx.x * 32;
#pragma unroll
    for (int j = threadIdx.y; j < 32; j += 8)
        out[(long)(yo0 + j) * R + xo] = t[threadIdx.x][j];
}

// ============================================================================
// bf16-split GEMM: C[M,N] = A @ B^T (+bias) (+res), A,B K-major.
// 128x128 tile, BK=32, 256 threads (8 warps of 64x32), double-buffered SMEM.
// SMEM stage (32KB): A_hi[128x32], A_lo, B_hi, B_lo as bf16, 64B rows,
// 16B-chunk XOR swizzle: phys_chunk = log_chunk ^ (row & 3).
// tstore: transposed store for V proj: addr=(m>>10)*8388608 + n*1024 + (m&1023)
// ============================================================================
#define OFF_A_HI 0
#define OFF_A_LO 8192
#define OFF_B_HI 16384
#define OFF_B_LO 24576
#define STAGE 32768
#define GEMM_SMEM (2 * STAGE)

__global__ void __launch_bounds__(256)
tc_gemm(const float* __restrict__ A, const float* __restrict__ B,
        const float* __restrict__ bias, const float* __restrict__ res,
        float* __restrict__ C,
        int K, int lda, int ldb, int ldc,
        long aO1, long aO2, long bO1, long bO2, long cO1, long cO2, int HD,
        int tstore)
{
    extern __shared__ char smem[];
    const uint32_t sb = smem_u32(smem);
    const int tid = threadIdx.x;
    const int wid = tid >> 5;
    const int lane = tid & 31;

    const int z = blockIdx.z;
    const int zb = z / HD, zh = z % HD;
    A += (long)zb * aO1 + (long)zh * aO2;
    B += (long)zb * bO1 + (long)zh * bO2;
    const long cOff = (long)zb * cO1 + (long)zh * cO2;

    const int row0 = blockIdx.y * 128;
    const int col0 = blockIdx.x * 128;

    // warp tile: rows [wr*64, +64), cols [wc*32, +32)
    const int wr = wid >> 2;
    const int wc = wid & 3;
    const int wm = wr * 64;
    const int wn = wc * 32;

    // ---- gmem->smem map: thread t covers row t>>1, float4s f=(t&1)*4+j ----
    const int grow = tid >> 1;
    const int gf0 = (tid & 1) * 4;
    const float* gA = A + (long)(row0 + grow) * lda + gf0 * 4;
    const float* gB = B + (long)(col0 + grow) * ldb + gf0 * 4;
    uint32_t stoff[4];
#pragma unroll
    for (int j = 0; j < 4; j++) {
        const int f = gf0 + j;
        stoff[j] = grow * 64 + (((f >> 1) ^ (grow & 3)) << 4) + (f & 1) * 8;
    }

    // ---- ldmatrix per-thread address components ----
    const int a_rowoff = ((lane >> 3) & 1) * 8 + (lane & 7);
    const int a_ksel = lane >> 4;
    const int a_swz = a_rowoff & 3;
    const int b_rowoff = (lane >> 4) * 8 + (lane & 7);
    const int b_ksel = (lane >> 3) & 1;
    const int b_swz = b_rowoff & 3;

    float acc[4][4][4];
#pragma unroll
    for (int mi = 0; mi < 4; mi++)
#pragma unroll
        for (int ni = 0; ni < 4; ni++)
#pragma unroll
            for (int e = 0; e < 4; e++) acc[mi][ni][e] = 0.f;

    const int nch = K >> 5;

    float4 av[4], bv[4];
#pragma unroll
    for (int j = 0; j < 4; j++) { av[j] = *(const float4*)(gA + j * 4); }
#pragma unroll
    for (int j = 0; j < 4; j++) { bv[j] = *(const float4*)(gB + j * 4); }
    {
        char* st = smem;
#pragma unroll
        for (int j = 0; j < 4; j++) {
            float4 x = av[j];
            float h0 = __uint_as_float(__float_as_uint(x.x) & 0xFFFF0000u);
            float h1 = __uint_as_float(__float_as_uint(x.y) & 0xFFFF0000u);
            float h2 = __uint_as_float(__float_as_uint(x.z) & 0xFFFF0000u);
            float h3 = __uint_as_float(__float_as_uint(x.w) & 0xFFFF0000u);
            uint2 hp = { pack_hi(x.x, x.y), pack_hi(x.z, x.w) };
            uint2 lp = { pack_rn(x.x - h0, x.y - h1), pack_rn(x.z - h2, x.w - h3) };
            *(uint2*)(st + OFF_A_HI + stoff[j]) = hp;
            *(uint2*)(st + OFF_A_LO + stoff[j]) = lp;
        }
#pragma unroll
        for (int j = 0; j < 4; j++) {
            float4 x = bv[j];
            float h0 = __uint_as_float(__float_as_uint(x.x) & 0xFFFF0000u);
            float h1 = __uint_as_float(__float_as_uint(x.y) & 0xFFFF0000u);
            float h2 = __uint_as_float(__float_as_uint(x.z) & 0xFFFF0000u);
            float h3 = __uint_as_float(__float_as_uint(x.w) & 0xFFFF0000u);
            uint2 hp = { pack_hi(x.x, x.y), pack_hi(x.z, x.w) };
            uint2 lp = { pack_rn(x.x - h0, x.y - h1), pack_rn(x.z - h2, x.w - h3) };
            *(uint2*)(st + OFF_B_HI + stoff[j]) = hp;
            *(uint2*)(st + OFF_B_LO + stoff[j]) = lp;
        }
    }
    __syncthreads();

    for (int ch = 0; ch < nch; ch++) {
        const int buf = ch & 1;
        const uint32_t stb = sb + buf * STAGE;
        const bool more = (ch + 1) < nch;

        if (more) {
            const int kt = (ch + 1) << 5;
#pragma unroll
            for (int j = 0; j < 4; j++) av[j] = *(const float4*)(gA + kt + j * 4);
#pragma unroll
            for (int j = 0; j < 4; j++) bv[j] = *(const float4*)(gB + kt + j * 4);
        }

        const uint32_t aBaseHi = stb + OFF_A_HI + (wm + a_rowoff) * 64;
        const uint32_t aBaseLo = stb + OFF_A_LO + (wm + a_rowoff) * 64;
#pragma unroll
        for (int ks = 0; ks < 2; ks++) {
            uint32_t bh[8], bl[8];
            {
                const uint32_t csel = ((uint32_t)(ks * 2 + b_ksel) ^ b_swz) << 4;
#pragma unroll
                for (int p = 0; p < 2; p++) {
                    const uint32_t ro = (wn + p * 16 + b_rowoff) * 64 + csel;
                    LDSM_X4(bh[p*4+0], bh[p*4+1], bh[p*4+2], bh[p*4+3],
                            stb + OFF_B_HI + ro);
                    LDSM_X4(bl[p*4+0], bl[p*4+1], bl[p*4+2], bl[p*4+3],
                            stb + OFF_B_LO + ro);
                }
            }
            const uint32_t acsel = ((uint32_t)(ks * 2 + a_ksel) ^ a_swz) << 4;
#pragma unroll
            for (int mi = 0; mi < 4; mi++) {
                uint32_t ah[4], al[4];
                LDSM_X4(ah[0], ah[1], ah[2], ah[3], aBaseHi + mi * 16 * 64 + acsel);
                LDSM_X4(al[0], al[1], al[2], al[3], aBaseLo + mi * 16 * 64 + acsel);
#pragma unroll
                for (int ni = 0; ni < 4; ni++)
                    MMA_BF16(acc[mi][ni], ah, bh[ni*2], bh[ni*2+1]);
#pragma unroll
                for (int ni = 0; ni < 4; ni++)
                    MMA_BF16(acc[mi][ni], ah, bl[ni*2], bl[ni*2+1]);
#pragma unroll
                for (int ni = 0; ni < 4; ni++)
                    MMA_BF16(acc[mi][ni], al, bh[ni*2], bh[ni*2+1]);
            }
        }

        if (more) {
            char* st = smem + (buf ^ 1) * STAGE;
#pragma unroll
            for (int j = 0; j < 4; j++) {
                float4 x = av[j];
                float h0 = __uint_as_float(__float_as_uint(x.x) & 0xFFFF0000u);
                float h1 = __uint_as_float(__float_as_uint(x.y) & 0xFFFF0000u);
                float h2 = __uint_as_float(__float_as_uint(x.z) & 0xFFFF0000u);
                float h3 = __uint_as_float(__float_as_uint(x.w) & 0xFFFF0000u);
                uint2 hp = { pack_hi(x.x, x.y), pack_hi(x.z, x.w) };
                uint2 lp = { pack_rn(x.x - h0, x.y - h1), pack_rn(x.z - h2, x.w - h3) };
                *(uint2*)(st + OFF_A_HI + stoff[j]) = hp;
                *(uint2*)(st + OFF_A_LO + stoff[j]) = lp;
            }
#pragma unroll
            for (int j = 0; j < 4; j++) {
                float4 x = bv[j];
                float h0 = __uint_as_float(__float_as_uint(x.x) & 0xFFFF0000u);
                float h1 = __uint_as_float(__float_as_uint(x.y) & 0xFFFF0000u);
                float h2 = __uint_as_float(__float_as_uint(x.z) & 0xFFFF0000u);
                float h3 = __uint_as_float(__float_as_uint(x.w) & 0xFFFF0000u);
                uint2 hp = { pack_hi(x.x, x.y), pack_hi(x.z, x.w) };
                uint2 lp = { pack_rn(x.x - h0, x.y - h1), pack_rn(x.z - h2, x.w - h3) };
                *(uint2*)(st + OFF_B_HI + stoff[j]) = hp;
                *(uint2*)(st + OFF_B_LO + stoff[j]) = lp;
            }
        }
        __syncthreads();
    }

    // ---- epilogue ----
    const int erow = lane >> 2;
    const int ecol = (lane & 3) * 2;
#pragma unroll
    for (int mi = 0; mi < 4; mi++) {
        const int r0 = row0 + wm + mi * 16 + erow;
        const int r1 = r0 + 8;
#pragma unroll
        for (int ni = 0; ni < 4; ni++) {
            const int c = col0 + wn + ni * 8 + ecol;
            float v0 = acc[mi][ni][0], v1 = acc[mi][ni][1];
            float v2 = acc[mi][ni][2], v3 = acc[mi][ni][3];
            if (bias) {
                const float b0 = bias[c], b1 = bias[c + 1];
                v0 += b0; v1 += b1; v2 += b0; v3 += b1;
            }
            if (res) {
                float2 q0 = *(const float2*)(res + cOff + (long)r0 * ldc + c);
                float2 q1 = *(const float2*)(res + cOff + (long)r1 * ldc + c);
                v0 += q0.x; v1 += q0.y; v2 += q1.x; v3 += q1.y;
            }
            if (!tstore) {
                float2 o0 = {v0, v1}, o1 = {v2, v3};
                *(float2*)(C + cOff + (long)r0 * ldc + c) = o0;
                *(float2*)(C + cOff + (long)r1 * ldc + c) = o1;
            } else {
                const long bb0 = (long)(r0 >> 10) * 8388608 + (r0 & 1023);
                const long bb1 = (long)(r1 >> 10) * 8388608 + (r1 & 1023);
                C[bb0 + (long)c * 1024]       = v0;
                C[bb0 + (long)(c + 1) * 1024] = v1;
                C[bb1 + (long)c * 1024]       = v2;
                C[bb1 + (long)(c + 1) * 1024] = v3;
            }
        }
    }
}

// ---------------- softmax (scale + mask + softmax over last dim) ----------------
__global__ void __launch_bounds__(256)
softmax_kernel(float* __restrict__ attn, const void* __restrict__ mask,
               int S, int H, float scale)
{
    const int i = blockIdx.x;
    const int z = blockIdx.y;
    const int b = z / H;
    float* p = attn + ((long)z * S + (long)i) * S;
    const long mbase = (long)b * S * S + (long)i * S;
    const int tid = threadIdx.x;
    const int mode = g_mask_mode;

    bool mk[4];
    if (mode == 0) {
        const unsigned char* mp = (const unsigned char*)mask + mbase;
#pragma unroll
        for (int r = 0; r < 4; r++) mk[r] = mp[tid + r * 256] != 0;
    } else if (mode == 1) {
        const int* mp = (const int*)mask + mbase;
#pragma unroll
        for (int r = 0; r < 4; r++) mk[r] = mp[tid + r * 256] != 0;
    } else {
        const float* mp = (const float*)mask + mbase;
#pragma unroll
        for (int r = 0; r < 4; r++) mk[r] = mp[tid + r * 256] != 0.f;
    }

    float v[4];
    float mx = -3.4e38f;
#pragma unroll
    for (int r = 0; r < 4; r++) {
        float s = p[tid + r * 256] * scale;
        if (mk[r]) s = -1e9f;
        v[r] = s;
        mx = fmaxf(mx, s);
    }
    __shared__ float red[256];
    red[tid] = mx; __syncthreads();
    for (int st = 128; st > 0; st >>= 1) {
        if (tid < st) red[tid] = fmaxf(red[tid], red[tid + st]);
        __syncthreads();
    }
    mx = red[0]; __syncthreads();
    float sum = 0.f;
#pragma unroll
    for (int r = 0; r < 4; r++) { v[r] = __expf(v[r] - mx); sum += v[r]; }
    red[tid] = sum; __syncthreads();
    for (int st = 128; st > 0; st >>= 1) {
        if (tid < st) red[tid] += red[tid + st];
        __syncthreads();
    }
    const float inv = 1.f / red[0];
#pragma unroll
    for (int r = 0; r < 4; r++) p[tid + r * 256] = v[r] * inv;
}

// ---------------- LayerNorm over D=512 ----------------
__global__ void __launch_bounds__(256)
layernorm_kernel(const float* __restrict__ x, const float* __restrict__ gamma,
                 const float* __restrict__ beta, float* __restrict__ out, int D)
{
    const int row = blockIdx.x;
    const float* p = x + (long)row * D;
    const int tid = threadIdx.x;
    const float a0 = p[tid];
    const float a1 = p[tid + 256];
    __shared__ float red[256];
    red[tid] = a0 + a1; __syncthreads();
    for (int st = 128; st > 0; st >>= 1) {
        if (tid < st) red[tid] += red[tid + st];
        __syncthreads();
    }
    const float mean = red[0] / (float)D; __syncthreads();
    const float d0 = a0 - mean, d1 = a1 - mean;
    red[tid] = d0 * d0 + d1 * d1; __syncthreads();
    for (int st = 128; st > 0; st >>= 1) {
        if (tid < st) red[tid] += red[tid + st];
        __syncthreads();
    }
    const float rstd = rsqrtf(red[0] / (float)D + 1e-5f);
    out[(long)row * D + tid]       = d0 * rstd * gamma[tid] + beta[tid];
    out[(long)row * D + tid + 256] = d1 * rstd * gamma[tid + 256] + beta[tid + 256];
}

// ---------------- launch ----------------
extern "C" void kernel_launch(void* const* d_in, const int* in_sizes, int n_in,
                              void* d_out, int out_size)
{
    const float* Q     = (const float*)d_in[0];
    const float* Kin   = (const float*)d_in[1];
    const float* Vin   = (const float*)d_in[2];
    const void*  Mask  = d_in[3];
    const float* Wq    = (const float*)d_in[4];
    const float* bq    = (const float*)d_in[5];
    const float* Wk    = (const float*)d_in[6];
    const float* bk    = (const float*)d_in[7];
    const float* Wv    = (const float*)d_in[8];
    const float* bv    = (const float*)d_in[9];
    const float* Wo    = (const float*)d_in[10];
    const float* bo    = (const float*)d_in[11];
    const float* gamma = (const float*)d_in[12];
    const float* beta  = (const float*)d_in[13];
    float* out = (float*)d_out;

    float *q, *k, *vt, *s, *o, *wqt, *wkt, *wvt, *wot;
    cudaGetSymbolAddress((void**)&q,   g_q);
    cudaGetSymbolAddress((void**)&k,   g_k);
    cudaGetSymbolAddress((void**)&vt,  g_vt);
    cudaGetSymbolAddress((void**)&s,   g_s);
    cudaGetSymbolAddress((void**)&o,   g_o);
    cudaGetSymbolAddress((void**)&wqt, g_wqt);
    cudaGetSymbolAddress((void**)&wkt, g_wkt);
    cudaGetSymbolAddress((void**)&wvt, g_wvt);
    cudaGetSymbolAddress((void**)&wot, g_wot);
    float* ctx = k;   // k-projection buffer is dead after the scores GEMM

    cudaFuncSetAttribute(tc_gemm, cudaFuncAttributeMaxDynamicSharedMemorySize, GEMM_SMEM);

    const int S = 1024, H = 8, D = 512, NH = 8192;
    const long SS = (long)S * S;
    dim3 blk(256);

    // 0. mask dtype + weight transposes
    detect_mask_kernel<<<1, 256>>>((const unsigned int*)Mask);
    transpose_kernel<<<dim3(NH / 32, D / 32), dim3(32, 8)>>>(Wq, wqt, D, NH);
    transpose_kernel<<<dim3(NH / 32, D / 32), dim3(32, 8)>>>(Wk, wkt, D, NH);
    transpose_kernel<<<dim3(NH / 32, D / 32), dim3(32, 8)>>>(Wv, wvt, D, NH);
    transpose_kernel<<<dim3(D / 32, NH / 32), dim3(32, 8)>>>(Wo, wot, NH, D);

    // 1. projections (NT): A[8192,512], B=W^T[8192,512]
    dim3 gp(NH / 128, 8192 / 128, 1);
    tc_gemm<<<gp, blk, GEMM_SMEM>>>(Q,   wqt, bq, nullptr, q,  D, D, D, NH,
                                    0, 0, 0, 0, 0, 0, 1, 0);
    tc_gemm<<<gp, blk, GEMM_SMEM>>>(Kin, wkt, bk, nullptr, k,  D, D, D, NH,
                                    0, 0, 0, 0, 0, 0, 1, 0);
    tc_gemm<<<gp, blk, GEMM_SMEM>>>(Vin, wvt, bv, nullptr, vt, D, D, D, 0,
                                    0, 0, 0, 0, 0, 0, 1, 1);   // transposed store

    // 2. scores[b,h] = q_bh @ k_bh^T
    dim3 gs(S / 128, S / 128, 64);
    tc_gemm<<<gs, blk, GEMM_SMEM>>>(q, k, nullptr, nullptr, s,
                                    1024, NH, NH, S,
                                    (long)S * NH, 1024,
                                    (long)S * NH, 1024,
                                    (long)H * SS, SS, H, 0);

    // 3. softmax (scale = 1/sqrt(dh) = 1/32)
    softmax_kernel<<<dim3(S, 64), blk>>>(s, Mask, S, H, 0.03125f);

    // 4. ctx[b,s,h,dh] = attn[b,h] @ v_t[b,h]^T  (ctx overwrites k buffer)
    tc_gemm<<<gs, blk, GEMM_SMEM>>>(s, vt, nullptr, nullptr, ctx,
                                    1024, S, S, NH,
                                    (long)H * SS, SS,
                                    (long)NH * S, (long)S * 1024,
                                    (long)S * NH, 1024, H, 0);

    // 5. out proj (NT): A=ctx[8192,8192], B=Wo^T[512,8192], +bo +Q residual
    dim3 go(D / 128, 8192 / 128, 1);
    tc_gemm<<<go, blk, GEMM_SMEM>>>(ctx, wot, bo, Q, o,
                                    NH, NH, NH, D,
                                    0, 0, 0, 0, 0, 0, 1, 0);

    // 6. LayerNorm
    layernorm_kernel<<<8192, blk>>>(o, gamma, beta, out, D);
}

// round 8
// speedup vs baseline: 3.3618x; 1.9210x over previous
#include <cuda_runtime.h>
#include <cstdint>

// ============================================================================
// MultiHeadAttention, reassociated-weights formulation + bf16 mma.sync GEMM.
// B=8, S=1024, D=512, H=8, DH=1024.
//
// Algebra: q.k^T = Q (Wq_h Wk_h^T) K^T ; ctx@Wo = sum_h (attn_h @ V)(Wv_h Wo_h).
//   M_h = Wq_h Wk_h^T  (512x512)   -> scores via K=512 instead of K=1024
//   N_h = Wv_h Wo_h    (512x512)   -> output via ctxv (K=512) + K=4096 reduce
// Bias handling (robust even though dataset biases are 0):
//   - softmax invariant to per-row consts; only bq.k_j term kept (vv array)
//   - v-bias+bo collapse to constant row crow (attn rows sum to 1)
// Dense FLOPs 550 GF -> 215 GF (2.56x less MMA work).
// GEMM kernel identical to the round-6 passing kernel (3-product bf16 split).
// ============================================================================

#define LDSM_X4(r0, r1, r2, r3, addr) \
    asm volatile("ldmatrix.sync.aligned.m8n8.x4.shared.b16 {%0,%1,%2,%3}, [%4];" \
                 : "=r"(r0), "=r"(r1), "=r"(r2), "=r"(r3) : "r"(addr))

#define MMA_BF16(d, a, b0, b1) \
    asm volatile("mma.sync.aligned.m16n8k16.row.col.f32.bf16.bf16.f32 " \
                 "{%0,%1,%2,%3}, {%4,%5,%6,%7}, {%8,%9}, {%0,%1,%2,%3};" \
                 : "+f"((d)[0]), "+f"((d)[1]), "+f"((d)[2]), "+f"((d)[3]) \
                 : "r"((a)[0]), "r"((a)[1]), "r"((a)[2]), "r"((a)[3]), \
                   "r"(b0), "r"(b1))

__device__ __forceinline__ uint32_t smem_u32(const void* p) {
    uint32_t a;
    asm("{ .reg .u64 t; cvta.to.shared.u64 t, %1; cvt.u32.u64 %0, t; }"
        : "=r"(a) : "l"(p));
    return a;
}
__device__ __forceinline__ uint32_t pack_hi(float x, float y) {
    uint32_t r;
    asm("prmt.b32 %0, %1, %2, 0x7632;"
        : "=r"(r) : "r"(__float_as_uint(x)), "r"(__float_as_uint(y)));
    return r;
}
__device__ __forceinline__ uint32_t pack_rn(float x, float y) {
    uint32_t r;
    asm("cvt.rn.bf16x2.f32 %0, %1, %2;" : "=r"(r) : "f"(y), "f"(x));
    return r;
}

// ---------------- device scratch (~576 MB total) ----------------
__device__ __align__(256) float g_qm  [(size_t)8 * 8192 * 512];   // 128 MB [h][i][q]
__device__ __align__(256) float g_s   [(size_t)64 * 1024 * 1024]; // 256 MB scores/attn
__device__ __align__(256) float g_ctxv[(size_t)8192 * 4096];      // 128 MB [i][(h,p)]
__device__ __align__(256) float g_vt  [(size_t)8 * 512 * 1024];   // 16 MB  V^T per b
__device__ __align__(256) float g_wot [(size_t)512 * 8192];       // 16 MB  Wo^T
__device__ __align__(256) float g_mt  [(size_t)8 * 512 * 512];    // 8 MB   [h][q][p]=M_h[p,q]
__device__ __align__(256) float g_nt  [(size_t)512 * 4096];       // 8 MB   [o][(h,p)]=N_h[p,o]
__device__ __align__(256) float g_o   [(size_t)8192 * 512];       // 16 MB  pre-LN
__device__ __align__(256) float g_vv  [8 * 8192];                 // bias col term (scaled)
__device__ __align__(256) float g_w2  [8 * 512];
__device__ __align__(256) float g_crow[512];
__device__ int g_mask_mode;

// ---------------- mask dtype detection ----------------
__global__ void detect_mask_kernel(const unsigned int* __restrict__ m) {
    __shared__ int sawFloat, sawByte;
    if (threadIdx.x == 0) { sawFloat = 0; sawByte = 0; }
    __syncthreads();
    for (int i = threadIdx.x; i < 4096; i += 256) {
        unsigned int w = m[i];
        if (w == 0x3F800000u) sawFloat = 1;
        else if (w > 1u) sawByte = 1;
    }
    __syncthreads();
    if (threadIdx.x == 0) g_mask_mode = sawFloat ? 2 : (sawByte ? 0 : 1);
}

// ---------------- batched transpose [R,C] -> [C,R] ----------------
__global__ void __launch_bounds__(256)
transpose_kernel(const float* __restrict__ in, float* __restrict__ out,
                 int R, int C, long inO, long outO) {
    in  += (long)blockIdx.z * inO;
    out += (long)blockIdx.z * outO;
    __shared__ float t[32][33];
    int x = blockIdx.x * 32 + threadIdx.x;
    int y0 = blockIdx.y * 32;
#pragma unroll
    for (int j = threadIdx.y; j < 32; j += 8)
        t[j][threadIdx.x] = in[(long)(y0 + j) * C + x];
    __syncthreads();
    int xo = blockIdx.y * 32 + threadIdx.x;
    int yo0 = blockIdx.x * 32;
#pragma unroll
    for (int j = threadIdx.y; j < 32; j += 8)
        out[(long)(yo0 + j) * R + xo] = t[threadIdx.x][j];
}

// ---------------- bias helper kernels (all-zero biases -> all-zero outputs) --
// w2[h][p] = sum_d Wk[p, h*1024+d] * bq[h*1024+d]
__global__ void w2_kernel(const float* __restrict__ Wk, const float* __restrict__ bq,
                          float* __restrict__ w2) {
    const int h = blockIdx.x, p = threadIdx.x;
    float s = 0.f;
    const float* row = Wk + (long)p * 8192 + h * 1024;
    const float* bv = bq + h * 1024;
    for (int d = 0; d < 1024; d++) s += row[d] * bv[d];
    w2[h * 512 + p] = s;
}
// vv[h][j] = scale * sum_p K[j,p] * w2[h][p]
__global__ void __launch_bounds__(256)
vv_kernel(const float* __restrict__ K, const float* __restrict__ w2,
          float* __restrict__ vv, float scale) {
    __shared__ float w2s[4096];
    for (int i = threadIdx.x; i < 4096; i += 256) w2s[i] = w2[i];
    __syncthreads();
    const int j = blockIdx.x * 32 + (threadIdx.x >> 3);
    const int h = threadIdx.x & 7;
    const float* kr = K + (long)j * 512;
    const float* wr = w2s + h * 512;
    float s = 0.f;
    for (int p = 0; p < 512; p++) s += kr[p] * wr[p];
    vv[h * 8192 + j] = s * scale;
}
// crow[o] = bo[o] + sum_m bv[m] * Wo[m, o]
__global__ void crow_kernel(const float* __restrict__ Wo, const float* __restrict__ bvv,
                            const float* __restrict__ bo, float* __restrict__ crow) {
    const int o = threadIdx.x;
    float s = bo[o];
    for (int m = 0; m < 8192; m++) s += bvv[m] * Wo[(long)m * 512 + o];
    crow[o] = s;
}

// ============================================================================
// bf16-split GEMM: C[M,N] = A @ B^T (+bias) (+res), A,B K-major. (unchanged)
// 128x128 tile, BK=32, 256 threads (8 warps of 64x32), double-buffered SMEM.
// ============================================================================
#define OFF_A_HI 0
#define OFF_A_LO 8192
#define OFF_B_HI 16384
#define OFF_B_LO 24576
#define STAGE 32768
#define GEMM_SMEM (2 * STAGE)

__global__ void __launch_bounds__(256)
tc_gemm(const float* __restrict__ A, const float* __restrict__ B,
        const float* __restrict__ bias, const float* __restrict__ res,
        float* __restrict__ C,
        int K, int lda, int ldb, int ldc,
        long aO1, long aO2, long bO1, long bO2, long cO1, long cO2, int HD)
{
    extern __shared__ char smem[];
    const uint32_t sb = smem_u32(smem);
    const int tid = threadIdx.x;
    const int wid = tid >> 5;
    const int lane = tid & 31;

    const int z = blockIdx.z;
    const int zb = z / HD, zh = z % HD;
    A += (long)zb * aO1 + (long)zh * aO2;
    B += (long)zb * bO1 + (long)zh * bO2;
    const long cOff = (long)zb * cO1 + (long)zh * cO2;

    const int row0 = blockIdx.y * 128;
    const int col0 = blockIdx.x * 128;

    const int wr = wid >> 2;
    const int wc = wid & 3;
    const int wm = wr * 64;
    const int wn = wc * 32;

    const int grow = tid >> 1;
    const int gf0 = (tid & 1) * 4;
    const float* gA = A + (long)(row0 + grow) * lda + gf0 * 4;
    const float* gB = B + (long)(col0 + grow) * ldb + gf0 * 4;
    uint32_t stoff[4];
#pragma unroll
    for (int j = 0; j < 4; j++) {
        const int f = gf0 + j;
        stoff[j] = grow * 64 + (((f >> 1) ^ (grow & 3)) << 4) + (f & 1) * 8;
    }

    const int a_rowoff = ((lane >> 3) & 1) * 8 + (lane & 7);
    const int a_ksel = lane >> 4;
    const int a_swz = a_rowoff & 3;
    const int b_rowoff = (lane >> 4) * 8 + (lane & 7);
    const int b_ksel = (lane >> 3) & 1;
    const int b_swz = b_rowoff & 3;

    float acc[4][4][4];
#pragma unroll
    for (int mi = 0; mi < 4; mi++)
#pragma unroll
        for (int ni = 0; ni < 4; ni++)
#pragma unroll
            for (int e = 0; e < 4; e++) acc[mi][ni][e] = 0.f;

    const int nch = K >> 5;

    float4 av[4], bv[4];
#pragma unroll
    for (int j = 0; j < 4; j++) { av[j] = *(const float4*)(gA + j * 4); }
#pragma unroll
    for (int j = 0; j < 4; j++) { bv[j] = *(const float4*)(gB + j * 4); }
    {
        char* st = smem;
#pragma unroll
        for (int j = 0; j < 4; j++) {
            float4 x = av[j];
            float h0 = __uint_as_float(__float_as_uint(x.x) & 0xFFFF0000u);
            float h1 = __uint_as_float(__float_as_uint(x.y) & 0xFFFF0000u);
            float h2 = __uint_as_float(__float_as_uint(x.z) & 0xFFFF0000u);
            float h3 = __uint_as_float(__float_as_uint(x.w) & 0xFFFF0000u);
            uint2 hp = { pack_hi(x.x, x.y), pack_hi(x.z, x.w) };
            uint2 lp = { pack_rn(x.x - h0, x.y - h1), pack_rn(x.z - h2, x.w - h3) };
            *(uint2*)(st + OFF_A_HI + stoff[j]) = hp;
            *(uint2*)(st + OFF_A_LO + stoff[j]) = lp;
        }
#pragma unroll
        for (int j = 0; j < 4; j++) {
            float4 x = bv[j];
            float h0 = __uint_as_float(__float_as_uint(x.x) & 0xFFFF0000u);
            float h1 = __uint_as_float(__float_as_uint(x.y) & 0xFFFF0000u);
            float h2 = __uint_as_float(__float_as_uint(x.z) & 0xFFFF0000u);
            float h3 = __uint_as_float(__float_as_uint(x.w) & 0xFFFF0000u);
            uint2 hp = { pack_hi(x.x, x.y), pack_hi(x.z, x.w) };
            uint2 lp = { pack_rn(x.x - h0, x.y - h1), pack_rn(x.z - h2, x.w - h3) };
            *(uint2*)(st + OFF_B_HI + stoff[j]) = hp;
            *(uint2*)(st + OFF_B_LO + stoff[j]) = lp;
        }
    }
    __syncthreads();

    for (int ch = 0; ch < nch; ch++) {
        const int buf = ch & 1;
        const uint32_t stb = sb + buf * STAGE;
        const bool more = (ch + 1) < nch;

        if (more) {
            const int kt = (ch + 1) << 5;
#pragma unroll
            for (int j = 0; j < 4; j++) av[j] = *(const float4*)(gA + kt + j * 4);
#pragma unroll
            for (int j = 0; j < 4; j++) bv[j] = *(const float4*)(gB + kt + j * 4);
        }

        const uint32_t aBaseHi = stb + OFF_A_HI + (wm + a_rowoff) * 64;
        const uint32_t aBaseLo = stb + OFF_A_LO + (wm + a_rowoff) * 64;
#pragma unroll
        for (int ks = 0; ks < 2; ks++) {
            uint32_t bh[8], bl[8];
            {
                const uint32_t csel = ((uint32_t)(ks * 2 + b_ksel) ^ b_swz) << 4;
#pragma unroll
                for (int p = 0; p < 2; p++) {
                    const uint32_t ro = (wn + p * 16 + b_rowoff) * 64 + csel;
                    LDSM_X4(bh[p*4+0], bh[p*4+1], bh[p*4+2], bh[p*4+3],
                            stb + OFF_B_HI + ro);
                    LDSM_X4(bl[p*4+0], bl[p*4+1], bl[p*4+2], bl[p*4+3],
                            stb + OFF_B_LO + ro);
                }
            }
            const uint32_t acsel = ((uint32_t)(ks * 2 + a_ksel) ^ a_swz) << 4;
#pragma unroll
            for (int mi = 0; mi < 4; mi++) {
                uint32_t ah[4], al[4];
                LDSM_X4(ah[0], ah[1], ah[2], ah[3], aBaseHi + mi * 16 * 64 + acsel);
                LDSM_X4(al[0], al[1], al[2], al[3], aBaseLo + mi * 16 * 64 + acsel);
#pragma unroll
                for (int ni = 0; ni < 4; ni++)
                    MMA_BF16(acc[mi][ni], ah, bh[ni*2], bh[ni*2+1]);
#pragma unroll
                for (int ni = 0; ni < 4; ni++)
                    MMA_BF16(acc[mi][ni], ah, bl[ni*2], bl[ni*2+1]);
#pragma unroll
                for (int ni = 0; ni < 4; ni++)
                    MMA_BF16(acc[mi][ni], al, bh[ni*2], bh[ni*2+1]);
            }
        }

        if (more) {
            char* st = smem + (buf ^ 1) * STAGE;
#pragma unroll
            for (int j = 0; j < 4; j++) {
                float4 x = av[j];
                float h0 = __uint_as_float(__float_as_uint(x.x) & 0xFFFF0000u);
                float h1 = __uint_as_float(__float_as_uint(x.y) & 0xFFFF0000u);
                float h2 = __uint_as_float(__float_as_uint(x.z) & 0xFFFF0000u);
                float h3 = __uint_as_float(__float_as_uint(x.w) & 0xFFFF0000u);
                uint2 hp = { pack_hi(x.x, x.y), pack_hi(x.z, x.w) };
                uint2 lp = { pack_rn(x.x - h0, x.y - h1), pack_rn(x.z - h2, x.w - h3) };
                *(uint2*)(st + OFF_A_HI + stoff[j]) = hp;
                *(uint2*)(st + OFF_A_LO + stoff[j]) = lp;
            }
#pragma unroll
            for (int j = 0; j < 4; j++) {
                float4 x = bv[j];
                float h0 = __uint_as_float(__float_as_uint(x.x) & 0xFFFF0000u);
                float h1 = __uint_as_float(__float_as_uint(x.y) & 0xFFFF0000u);
                float h2 = __uint_as_float(__float_as_uint(x.z) & 0xFFFF0000u);
                float h3 = __uint_as_float(__float_as_uint(x.w) & 0xFFFF0000u);
                uint2 hp = { pack_hi(x.x, x.y), pack_hi(x.z, x.w) };
                uint2 lp = { pack_rn(x.x - h0, x.y - h1), pack_rn(x.z - h2, x.w - h3) };
                *(uint2*)(st + OFF_B_HI + stoff[j]) = hp;
                *(uint2*)(st + OFF_B_LO + stoff[j]) = lp;
            }
        }
        __syncthreads();
    }

    // ---- epilogue ----
    const int erow = lane >> 2;
    const int ecol = (lane & 3) * 2;
#pragma unroll
    for (int mi = 0; mi < 4; mi++) {
        const int r0 = row0 + wm + mi * 16 + erow;
        const int r1 = r0 + 8;
#pragma unroll
        for (int ni = 0; ni < 4; ni++) {
            const int c = col0 + wn + ni * 8 + ecol;
            float v0 = acc[mi][ni][0], v1 = acc[mi][ni][1];
            float v2 = acc[mi][ni][2], v3 = acc[mi][ni][3];
            if (bias) {
                const float b0 = bias[c], b1 = bias[c + 1];
                v0 += b0; v1 += b1; v2 += b0; v3 += b1;
            }
            if (res) {
                float2 q0 = *(const float2*)(res + (long)r0 * ldc + c);
                float2 q1 = *(const float2*)(res + (long)r1 * ldc + c);
                v0 += q0.x; v1 += q0.y; v2 += q1.x; v3 += q1.y;
            }
            float2 o0 = {v0, v1}, o1 = {v2, v3};
            *(float2*)(C + cOff + (long)r0 * ldc + c) = o0;
            *(float2*)(C + cOff + (long)r1 * ldc + c) = o1;
        }
    }
}

// ---------------- softmax (scale + col-bias + mask + softmax) ----------------
__global__ void __launch_bounds__(256)
softmax_kernel(float* __restrict__ attn, const void* __restrict__ mask,
               const float* __restrict__ vv, int S, int H, float scale)
{
    const int i = blockIdx.x;
    const int z = blockIdx.y;
    const int b = z / H;
    const int h = z % H;
    float* p = attn + ((long)z * S + (long)i) * S;
    const float* vsp = vv + h * 8192 + b * 1024;
    const long mbase = (long)b * S * S + (long)i * S;
    const int tid = threadIdx.x;
    const int mode = g_mask_mode;

    bool mk[4];
    if (mode == 0) {
        const unsigned char* mp = (const unsigned char*)mask + mbase;
#pragma unroll
        for (int r = 0; r < 4; r++) mk[r] = mp[tid + r * 256] != 0;
    } else if (mode == 1) {
        const int* mp = (const int*)mask + mbase;
#pragma unroll
        for (int r = 0; r < 4; r++) mk[r] = mp[tid + r * 256] != 0;
    } else {
        const float* mp = (const float*)mask + mbase;
#pragma unroll
        for (int r = 0; r < 4; r++) mk[r] = mp[tid + r * 256] != 0.f;
    }

    float v[4];
    float mx = -3.4e38f;
#pragma unroll
    for (int r = 0; r < 4; r++) {
        const int j = tid + r * 256;
        float s = p[j] * scale + vsp[j];
        if (mk[r]) s = -1e9f;
        v[r] = s;
        mx = fmaxf(mx, s);
    }
    __shared__ float red[256];
    red[tid] = mx; __syncthreads();
    for (int st = 128; st > 0; st >>= 1) {
        if (tid < st) red[tid] = fmaxf(red[tid], red[tid + st]);
        __syncthreads();
    }
    mx = red[0]; __syncthreads();
    float sum = 0.f;
#pragma unroll
    for (int r = 0; r < 4; r++) { v[r] = __expf(v[r] - mx); sum += v[r]; }
    red[tid] = sum; __syncthreads();
    for (int st = 128; st > 0; st >>= 1) {
        if (tid < st) red[tid] += red[tid + st];
        __syncthreads();
    }
    const float inv = 1.f / red[0];
#pragma unroll
    for (int r = 0; r < 4; r++) p[tid + r * 256] = v[r] * inv;
}

// ---------------- LayerNorm over D=512 ----------------
__global__ void __launch_bounds__(256)
layernorm_kernel(const float* __restrict__ x, const float* __restrict__ gamma,
                 const float* __restrict__ beta, float* __restrict__ out, int D)
{
    const int row = blockIdx.x;
    const float* p = x + (long)row * D;
    const int tid = threadIdx.x;
    const float a0 = p[tid];
    const float a1 = p[tid + 256];
    __shared__ float red[256];
    red[tid] = a0 + a1; __syncthreads();
    for (int st = 128; st > 0; st >>= 1) {
        if (tid < st) red[tid] += red[tid + st];
        __syncthreads();
    }
    const float mean = red[0] / (float)D; __syncthreads();
    const float d0 = a0 - mean, d1 = a1 - mean;
    red[tid] = d0 * d0 + d1 * d1; __syncthreads();
    for (int st = 128; st > 0; st >>= 1) {
        if (tid < st) red[tid] += red[tid + st];
        __syncthreads();
    }
    const float rstd = rsqrtf(red[0] / (float)D + 1e-5f);
    out[(long)row * D + tid]       = d0 * rstd * gamma[tid] + beta[tid];
    out[(long)row * D + tid + 256] = d1 * rstd * gamma[tid + 256] + beta[tid + 256];
}

// ---------------- launch ----------------
extern "C" void kernel_launch(void* const* d_in, const int* in_sizes, int n_in,
                              void* d_out, int out_size)
{
    const float* Q     = (const float*)d_in[0];
    const float* Kin   = (const float*)d_in[1];
    const float* Vin   = (const float*)d_in[2];
    const void*  Mask  = d_in[3];
    const float* Wq    = (const float*)d_in[4];
    const float* bq    = (const float*)d_in[5];
    const float* Wk    = (const float*)d_in[6];
    const float* bv    = (const float*)d_in[9];
    const float* Wv    = (const float*)d_in[8];
    const float* Wo    = (const float*)d_in[10];
    const float* bo    = (const float*)d_in[11];
    const float* gamma = (const float*)d_in[12];
    const float* beta  = (const float*)d_in[13];
    float* out = (float*)d_out;

    float *qm, *s, *ctxv, *vt, *wot, *mt, *nt, *o, *vv, *w2, *crow;
    cudaGetSymbolAddress((void**)&qm,   g_qm);
    cudaGetSymbolAddress((void**)&s,    g_s);
    cudaGetSymbolAddress((void**)&ctxv, g_ctxv);
    cudaGetSymbolAddress((void**)&vt,   g_vt);
    cudaGetSymbolAddress((void**)&wot,  g_wot);
    cudaGetSymbolAddress((void**)&mt,   g_mt);
    cudaGetSymbolAddress((void**)&nt,   g_nt);
    cudaGetSymbolAddress((void**)&o,    g_o);
    cudaGetSymbolAddress((void**)&vv,   g_vv);
    cudaGetSymbolAddress((void**)&w2,   g_w2);
    cudaGetSymbolAddress((void**)&crow, g_crow);

    cudaFuncSetAttribute(tc_gemm, cudaFuncAttributeMaxDynamicSharedMemorySize, GEMM_SMEM);

    const int S = 1024, H = 8;
    const long SS = (long)S * S;
    dim3 blk(256);

    // 0. mask dtype; transposes; bias helpers
    detect_mask_kernel<<<1, 256>>>((const unsigned int*)Mask);
    // Wo [8192,512] -> wot [512,8192]
    transpose_kernel<<<dim3(16, 256, 1), dim3(32, 8)>>>(Wo, wot, 8192, 512, 0, 0);
    // V [b][1024,512] -> vt [b][512,1024]
    transpose_kernel<<<dim3(16, 32, 8), dim3(32, 8)>>>(Vin, vt, 1024, 512,
                                                       524288, 524288);
    w2_kernel<<<8, 512>>>(Wk, bq, w2);
    vv_kernel<<<256, 256>>>(Kin, w2, vv, 0.03125f);
    crow_kernel<<<1, 512>>>(Wo, bv, bo, crow);

    // G1: mt[h][q][p] = sum_d Wk[q,h*1024+d] * Wq[p,h*1024+d]  (= M_h[p,q])
    tc_gemm<<<dim3(4, 4, 8), blk, GEMM_SMEM>>>(Wk, Wq, nullptr, nullptr, mt,
        1024, 8192, 8192, 512,
        0, 1024, 0, 1024, 0, (long)512 * 512, 8);

    // G2: qm[h][i][q] = sum_p Q[i,p] * mt[h][q][p] = (Q @ M_h)[i,q]
    tc_gemm<<<dim3(4, 64, 8), blk, GEMM_SMEM>>>(Q, mt, nullptr, nullptr, qm,
        512, 512, 512, 512,
        0, 0, 0, (long)512 * 512, 0, (long)8192 * 512, 8);

    // G3: s[b][h][i][j] = sum_q qm[h][b*1024+i][q] * K[b*1024+j][q]
    tc_gemm<<<dim3(8, 8, 64), blk, GEMM_SMEM>>>(qm, Kin, nullptr, nullptr, s,
        512, 512, 512, 1024,
        (long)1024 * 512, (long)8192 * 512,
        (long)1024 * 512, 0,
        (long)H * SS, SS, 8);

    // softmax with column bias (scale = 1/sqrt(dh) = 1/32)
    softmax_kernel<<<dim3(S, 64), blk>>>(s, Mask, vv, S, H, 0.03125f);

    // G5: ctxv[b*1024+i][h*512+p] = sum_j attn[b,h][i,j] * vt[b][p][j]
    tc_gemm<<<dim3(4, 8, 64), blk, GEMM_SMEM>>>(s, vt, nullptr, nullptr, ctxv,
        1024, 1024, 1024, 4096,
        (long)H * SS, SS,
        (long)512 * 1024, 0,
        (long)1024 * 4096, 512, 8);

    // G6: nt[o][h*512+p] = sum_d wot[o,h*1024+d] * Wv[p,h*1024+d]  (= N_h[p,o])
    tc_gemm<<<dim3(4, 4, 8), blk, GEMM_SMEM>>>(wot, Wv, nullptr, nullptr, nt,
        1024, 8192, 8192, 4096,
        0, 1024, 0, 1024, 0, 512, 8);

    // G7: o[i][o'] = sum_{hp} ctxv[i][hp] * nt[o'][hp] + crow[o'] + Q[i][o']
    tc_gemm<<<dim3(4, 64, 1), blk, GEMM_SMEM>>>(ctxv, nt, crow, Q, o,
        4096, 4096, 4096, 512,
        0, 0, 0, 0, 0, 0, 1);

    // LayerNorm
    layernorm_kernel<<<8192, blk>>>(o, gamma, beta, out, 512);
}

// round 11
// speedup vs baseline: 4.2294x; 1.2581x over previous
#include <cuda_runtime.h>
#include <cstdint>

// ============================================================================
// MultiHeadAttention, reassociated-weights formulation + bf16 mma.sync GEMM.
// B=8, S=1024, D=512, H=8, DH=1024.
//
// Algebra: q.k^T = Q (Wq_h Wk_h^T) K^T ; ctx@Wo = sum_h (attn_h @ V)(Wv_h Wo_h).
// Round 11: resubmission of the audited round-9/10 kernel (broker flake is
// ~60% i.i.d. per round, content-independent; keep submitting the best
// audited candidate). Parallelized w2/vv/crow helpers; GEMM = round-8
// passing version. G1 at launch index 5 for ncu -s 5.
// ============================================================================

#define LDSM_X4(r0, r1, r2, r3, addr) \
    asm volatile("ldmatrix.sync.aligned.m8n8.x4.shared.b16 {%0,%1,%2,%3}, [%4];" \
                 : "=r"(r0), "=r"(r1), "=r"(r2), "=r"(r3) : "r"(addr))

#define MMA_BF16(d, a, b0, b1) \
    asm volatile("mma.sync.aligned.m16n8k16.row.col.f32.bf16.bf16.f32 " \
                 "{%0,%1,%2,%3}, {%4,%5,%6,%7}, {%8,%9}, {%0,%1,%2,%3};" \
                 : "+f"((d)[0]), "+f"((d)[1]), "+f"((d)[2]), "+f"((d)[3]) \
                 : "r"((a)[0]), "r"((a)[1]), "r"((a)[2]), "r"((a)[3]), \
                   "r"(b0), "r"(b1))

__device__ __forceinline__ uint32_t smem_u32(const void* p) {
    uint32_t a;
    asm("{ .reg .u64 t; cvta.to.shared.u64 t, %1; cvt.u32.u64 %0, t; }"
        : "=r"(a) : "l"(p));
    return a;
}
__device__ __forceinline__ uint32_t pack_hi(float x, float y) {
    uint32_t r;
    asm("prmt.b32 %0, %1, %2, 0x7632;"
        : "=r"(r) : "r"(__float_as_uint(x)), "r"(__float_as_uint(y)));
    return r;
}
__device__ __forceinline__ uint32_t pack_rn(float x, float y) {
    uint32_t r;
    asm("cvt.rn.bf16x2.f32 %0, %1, %2;" : "=r"(r) : "f"(y), "f"(x));
    return r;
}

// ---------------- device scratch ----------------
__device__ __align__(256) float g_qm  [(size_t)8 * 8192 * 512];   // [h][i][q]
__device__ __align__(256) float g_s   [(size_t)64 * 1024 * 1024]; // scores/attn
__device__ __align__(256) float g_ctxv[(size_t)8192 * 4096];      // [i][(h,p)]
__device__ __align__(256) float g_vt  [(size_t)8 * 512 * 1024];   // V^T per b
__device__ __align__(256) float g_wot [(size_t)512 * 8192];       // Wo^T
__device__ __align__(256) float g_mt  [(size_t)8 * 512 * 512];    // [h][q][p]=M_h[p,q]
__device__ __align__(256) float g_nt  [(size_t)512 * 4096];       // [o][(h,p)]=N_h[p,o]
__device__ __align__(256) float g_o   [(size_t)8192 * 512];       // pre-LN
__device__ __align__(256) float g_vv  [8 * 8192];                 // bias col term (scaled)
__device__ __align__(256) float g_w2  [8 * 512];
__device__ __align__(256) float g_cpart[128 * 512];               // crow partials
__device__ __align__(256) float g_crow[512];
__device__ int g_mask_mode;

// ---------------- mask dtype detection ----------------
__global__ void detect_mask_kernel(const unsigned int* __restrict__ m) {
    __shared__ int sawFloat, sawByte;
    if (threadIdx.x == 0) { sawFloat = 0; sawByte = 0; }
    __syncthreads();
    for (int i = threadIdx.x; i < 4096; i += 256) {
        unsigned int w = m[i];
        if (w == 0x3F800000u) sawFloat = 1;
        else if (w > 1u) sawByte = 1;
    }
    __syncthreads();
    if (threadIdx.x == 0) g_mask_mode = sawFloat ? 2 : (sawByte ? 0 : 1);
}

// ---------------- batched transpose [R,C] -> [C,R] ----------------
__global__ void __launch_bounds__(256)
transpose_kernel(const float* __restrict__ in, float* __restrict__ out,
                 int R, int C, long inO, long outO) {
    in  += (long)blockIdx.z * inO;
    out += (long)blockIdx.z * outO;
    __shared__ float t[32][33];
    int x = blockIdx.x * 32 + threadIdx.x;
    int y0 = blockIdx.y * 32;
#pragma unroll
    for (int j = threadIdx.y; j < 32; j += 8)
        t[j][threadIdx.x] = in[(long)(y0 + j) * C + x];
    __syncthreads();
    int xo = blockIdx.y * 32 + threadIdx.x;
    int yo0 = blockIdx.x * 32;
#pragma unroll
    for (int j = threadIdx.y; j < 32; j += 8)
        out[(long)(yo0 + j) * R + xo] = t[threadIdx.x][j];
}

// ---------------- bias helper kernels (parallelized) ----------------
// w2[h][p] = sum_d Wk[p, h*1024+d] * bq[h*1024+d]; one block per (p,h)
__global__ void __launch_bounds__(256)
w2_kernel(const float* __restrict__ Wk, const float* __restrict__ bq,
          float* __restrict__ w2) {
    const int p = blockIdx.x, h = blockIdx.y;
    const int tid = threadIdx.x;
    const float4 a = *(const float4*)(Wk + (long)p * 8192 + h * 1024 + tid * 4);
    const float4 b = *(const float4*)(bq + h * 1024 + tid * 4);
    float s = a.x * b.x + a.y * b.y + a.z * b.z + a.w * b.w;
    __shared__ float red[256];
    red[tid] = s; __syncthreads();
    for (int st = 128; st > 0; st >>= 1) {
        if (tid < st) red[tid] += red[tid + st];
        __syncthreads();
    }
    if (tid == 0) w2[h * 512 + p] = red[0];
}
// vv[h][j] = scale * sum_p K[j,p] * w2[h][p]; one block per j, warp per h
__global__ void __launch_bounds__(256)
vv_kernel(const float* __restrict__ K, const float* __restrict__ w2,
          float* __restrict__ vv, float scale) {
    const int j = blockIdx.x;
    const int tid = threadIdx.x;
    const int wid = tid >> 5, lane = tid & 31;
    __shared__ float kr[512];
    for (int i = tid; i < 512; i += 256) kr[i] = K[(long)j * 512 + i];
    __syncthreads();
    const float* wr = w2 + wid * 512;
    float s = 0.f;
    for (int p = lane; p < 512; p += 32) s += kr[p] * wr[p];
#pragma unroll
    for (int o = 16; o > 0; o >>= 1) s += __shfl_down_sync(0xFFFFFFFFu, s, o);
    if (lane == 0) vv[wid * 8192 + j] = s * scale;
}
// crow phase A: cpart[blk][o] = sum over 64 m-rows of bv[m]*Wo[m,o]
__global__ void __launch_bounds__(256)
crowA_kernel(const float* __restrict__ Wo, const float* __restrict__ bvv,
             float* __restrict__ cpart) {
    const int m0 = blockIdx.x * 64;
    const int tid = threadIdx.x;
    __shared__ float bvs[64];
    if (tid < 64) bvs[tid] = bvv[m0 + tid];
    __syncthreads();
    float s0 = 0.f, s1 = 0.f;
    for (int m = 0; m < 64; m++) {
        const float b = bvs[m];
        const float* row = Wo + (long)(m0 + m) * 512;
        s0 += b * row[tid];
        s1 += b * row[tid + 256];
    }
    cpart[blockIdx.x * 512 + tid] = s0;
    cpart[blockIdx.x * 512 + tid + 256] = s1;
}
// crow phase B: crow[o] = bo[o] + sum_blk cpart[blk][o]
__global__ void crowB_kernel(const float* __restrict__ cpart,
                             const float* __restrict__ bo, float* __restrict__ crow) {
    const int o = threadIdx.x;
    float s = bo[o];
    for (int b = 0; b < 128; b++) s += cpart[b * 512 + o];
    crow[o] = s;
}

// ============================================================================
// bf16-split GEMM: C[M,N] = A @ B^T (+bias) (+res), A,B K-major. (unchanged)
// 128x128 tile, BK=32, 256 threads (8 warps of 64x32), double-buffered SMEM.
// ============================================================================
#define OFF_A_HI 0
#define OFF_A_LO 8192
#define OFF_B_HI 16384
#define OFF_B_LO 24576
#define STAGE 32768
#define GEMM_SMEM (2 * STAGE)

__global__ void __launch_bounds__(256)
tc_gemm(const float* __restrict__ A, const float* __restrict__ B,
        const float* __restrict__ bias, const float* __restrict__ res,
        float* __restrict__ C,
        int K, int lda, int ldb, int ldc,
        long aO1, long aO2, long bO1, long bO2, long cO1, long cO2, int HD)
{
    extern __shared__ char smem[];
    const uint32_t sb = smem_u32(smem);
    const int tid = threadIdx.x;
    const int wid = tid >> 5;
    const int lane = tid & 31;

    const int z = blockIdx.z;
    const int zb = z / HD, zh = z % HD;
    A += (long)zb * aO1 + (long)zh * aO2;
    B += (long)zb * bO1 + (long)zh * bO2;
    const long cOff = (long)zb * cO1 + (long)zh * cO2;

    const int row0 = blockIdx.y * 128;
    const int col0 = blockIdx.x * 128;

    const int wr = wid >> 2;
    const int wc = wid & 3;
    const int wm = wr * 64;
    const int wn = wc * 32;

    const int grow = tid >> 1;
    const int gf0 = (tid & 1) * 4;
    const float* gA = A + (long)(row0 + grow) * lda + gf0 * 4;
    const float* gB = B + (long)(col0 + grow) * ldb + gf0 * 4;
    uint32_t stoff[4];
#pragma unroll
    for (int j = 0; j < 4; j++) {
        const int f = gf0 + j;
        stoff[j] = grow * 64 + (((f >> 1) ^ (grow & 3)) << 4) + (f & 1) * 8;
    }

    const int a_rowoff = ((lane >> 3) & 1) * 8 + (lane & 7);
    const int a_ksel = lane >> 4;
    const int a_swz = a_rowoff & 3;
    const int b_rowoff = (lane >> 4) * 8 + (lane & 7);
    const int b_ksel = (lane >> 3) & 1;
    const int b_swz = b_rowoff & 3;

    float acc[4][4][4];
#pragma unroll
    for (int mi = 0; mi < 4; mi++)
#pragma unroll
        for (int ni = 0; ni < 4; ni++)
#pragma unroll
            for (int e = 0; e < 4; e++) acc[mi][ni][e] = 0.f;

    const int nch = K >> 5;

    float4 av[4], bv[4];
#pragma unroll
    for (int j = 0; j < 4; j++) { av[j] = *(const float4*)(gA + j * 4); }
#pragma unroll
    for (int j = 0; j < 4; j++) { bv[j] = *(const float4*)(gB + j * 4); }
    {
        char* st = smem;
#pragma unroll
        for (int j = 0; j < 4; j++) {
            float4 x = av[j];
            float h0 = __uint_as_float(__float_as_uint(x.x) & 0xFFFF0000u);
            float h1 = __uint_as_float(__float_as_uint(x.y) & 0xFFFF0000u);
            float h2 = __uint_as_float(__float_as_uint(x.z) & 0xFFFF0000u);
            float h3 = __uint_as_float(__float_as_uint(x.w) & 0xFFFF0000u);
            uint2 hp = { pack_hi(x.x, x.y), pack_hi(x.z, x.w) };
            uint2 lp = { pack_rn(x.x - h0, x.y - h1), pack_rn(x.z - h2, x.w - h3) };
            *(uint2*)(st + OFF_A_HI + stoff[j]) = hp;
            *(uint2*)(st + OFF_A_LO + stoff[j]) = lp;
        }
#pragma unroll
        for (int j = 0; j < 4; j++) {
            float4 x = bv[j];
            float h0 = __uint_as_float(__float_as_uint(x.x) & 0xFFFF0000u);
            float h1 = __uint_as_float(__float_as_uint(x.y) & 0xFFFF0000u);
            float h2 = __uint_as_float(__float_as_uint(x.z) & 0xFFFF0000u);
            float h3 = __uint_as_float(__float_as_uint(x.w) & 0xFFFF0000u);
            uint2 hp = { pack_hi(x.x, x.y), pack_hi(x.z, x.w) };
            uint2 lp = { pack_rn(x.x - h0, x.y - h1), pack_rn(x.z - h2, x.w - h3) };
            *(uint2*)(st + OFF_B_HI + stoff[j]) = hp;
            *(uint2*)(st + OFF_B_LO + stoff[j]) = lp;
        }
    }
    __syncthreads();

    for (int ch = 0; ch < nch; ch++) {
        const int buf = ch & 1;
        const uint32_t stb = sb + buf * STAGE;
        const bool more = (ch + 1) < nch;

        if (more) {
            const int kt = (ch + 1) << 5;
#pragma unroll
            for (int j = 0; j < 4; j++) av[j] = *(const float4*)(gA + kt + j * 4);
#pragma unroll
            for (int j = 0; j < 4; j++) bv[j] = *(const float4*)(gB + kt + j * 4);
        }

        const uint32_t aBaseHi = stb + OFF_A_HI + (wm + a_rowoff) * 64;
        const uint32_t aBaseLo = stb + OFF_A_LO + (wm + a_rowoff) * 64;
#pragma unroll
        for (int ks = 0; ks < 2; ks++) {
            uint32_t bh[8], bl[8];
            {
                const uint32_t csel = ((uint32_t)(ks * 2 + b_ksel) ^ b_swz) << 4;
#pragma unroll
                for (int p = 0; p < 2; p++) {
                    const uint32_t ro = (wn + p * 16 + b_rowoff) * 64 + csel;
                    LDSM_X4(bh[p*4+0], bh[p*4+1], bh[p*4+2], bh[p*4+3],
                            stb + OFF_B_HI + ro);
                    LDSM_X4(bl[p*4+0], bl[p*4+1], bl[p*4+2], bl[p*4+3],
                            stb + OFF_B_LO + ro);
                }
            }
            const uint32_t acsel = ((uint32_t)(ks * 2 + a_ksel) ^ a_swz) << 4;
#pragma unroll
            for (int mi = 0; mi < 4; mi++) {
                uint32_t ah[4], al[4];
                LDSM_X4(ah[0], ah[1], ah[2], ah[3], aBaseHi + mi * 16 * 64 + acsel);
                LDSM_X4(al[0], al[1], al[2], al[3], aBaseLo + mi * 16 * 64 + acsel);
#pragma unroll
                for (int ni = 0; ni < 4; ni++)
                    MMA_BF16(acc[mi][ni], ah, bh[ni*2], bh[ni*2+1]);
#pragma unroll
                for (int ni = 0; ni < 4; ni++)
                    MMA_BF16(acc[mi][ni], ah, bl[ni*2], bl[ni*2+1]);
#pragma unroll
                for (int ni = 0; ni < 4; ni++)
                    MMA_BF16(acc[mi][ni], al, bh[ni*2], bh[ni*2+1]);
            }
        }

        if (more) {
            char* st = smem + (buf ^ 1) * STAGE;
#pragma unroll
            for (int j = 0; j < 4; j++) {
                float4 x = av[j];
                float h0 = __uint_as_float(__float_as_uint(x.x) & 0xFFFF0000u);
                float h1 = __uint_as_float(__float_as_uint(x.y) & 0xFFFF0000u);
                float h2 = __uint_as_float(__float_as_uint(x.z) & 0xFFFF0000u);
                float h3 = __uint_as_float(__float_as_uint(x.w) & 0xFFFF0000u);
                uint2 hp = { pack_hi(x.x, x.y), pack_hi(x.z, x.w) };
                uint2 lp = { pack_rn(x.x - h0, x.y - h1), pack_rn(x.z - h2, x.w - h3) };
                *(uint2*)(st + OFF_A_HI + stoff[j]) = hp;
                *(uint2*)(st + OFF_A_LO + stoff[j]) = lp;
            }
#pragma unroll
            for (int j = 0; j < 4; j++) {
                float4 x = bv[j];
                float h0 = __uint_as_float(__float_as_uint(x.x) & 0xFFFF0000u);
                float h1 = __uint_as_float(__float_as_uint(x.y) & 0xFFFF0000u);
                float h2 = __uint_as_float(__float_as_uint(x.z) & 0xFFFF0000u);
                float h3 = __uint_as_float(__float_as_uint(x.w) & 0xFFFF0000u);
                uint2 hp = { pack_hi(x.x, x.y), pack_hi(x.z, x.w) };
                uint2 lp = { pack_rn(x.x - h0, x.y - h1), pack_rn(x.z - h2, x.w - h3) };
                *(uint2*)(st + OFF_B_HI + stoff[j]) = hp;
                *(uint2*)(st + OFF_B_LO + stoff[j]) = lp;
            }
        }
        __syncthreads();
    }

    // ---- epilogue ----
    const int erow = lane >> 2;
    const int ecol = (lane & 3) * 2;
#pragma unroll
    for (int mi = 0; mi < 4; mi++) {
        const int r0 = row0 + wm + mi * 16 + erow;
        const int r1 = r0 + 8;
#pragma unroll
        for (int ni = 0; ni < 4; ni++) {
            const int c = col0 + wn + ni * 8 + ecol;
            float v0 = acc[mi][ni][0], v1 = acc[mi][ni][1];
            float v2 = acc[mi][ni][2], v3 = acc[mi][ni][3];
            if (bias) {
                const float b0 = bias[c], b1 = bias[c + 1];
                v0 += b0; v1 += b1; v2 += b0; v3 += b1;
            }
            if (res) {
                float2 q0 = *(const float2*)(res + (long)r0 * ldc + c);
                float2 q1 = *(const float2*)(res + (long)r1 * ldc + c);
                v0 += q0.x; v1 += q0.y; v2 += q1.x; v3 += q1.y;
            }
            float2 o0 = {v0, v1}, o1 = {v2, v3};
            *(float2*)(C + cOff + (long)r0 * ldc + c) = o0;
            *(float2*)(C + cOff + (long)r1 * ldc + c) = o1;
        }
    }
}

// ---------------- softmax (scale + col-bias + mask + softmax) ----------------
__global__ void __launch_bounds__(256)
softmax_kernel(float* __restrict__ attn, const void* __restrict__ mask,
               const float* __restrict__ vv, int S, int H, float scale)
{
    const int i = blockIdx.x;
    const int z = blockIdx.y;
    const int b = z / H;
    const int h = z % H;
    float* p = attn + ((long)z * S + (long)i) * S;
    const float* vsp = vv + h * 8192 + b * 1024;
    const long mbase = (long)b * S * S + (long)i * S;
    const int tid = threadIdx.x;
    const int mode = g_mask_mode;

    bool mk[4];
    if (mode == 0) {
        const unsigned char* mp = (const unsigned char*)mask + mbase;
#pragma unroll
        for (int r = 0; r < 4; r++) mk[r] = mp[tid + r * 256] != 0;
    } else if (mode == 1) {
        const int* mp = (const int*)mask + mbase;
#pragma unroll
        for (int r = 0; r < 4; r++) mk[r] = mp[tid + r * 256] != 0;
    } else {
        const float* mp = (const float*)mask + mbase;
#pragma unroll
        for (int r = 0; r < 4; r++) mk[r] = mp[tid + r * 256] != 0.f;
    }

    float v[4];
    float mx = -3.4e38f;
#pragma unroll
    for (int r = 0; r < 4; r++) {
        const int j = tid + r * 256;
        float s = p[j] * scale + vsp[j];
        if (mk[r]) s = -1e9f;
        v[r] = s;
        mx = fmaxf(mx, s);
    }
    __shared__ float red[256];
    red[tid] = mx; __syncthreads();
    for (int st = 128; st > 0; st >>= 1) {
        if (tid < st) red[tid] = fmaxf(red[tid], red[tid + st]);
        __syncthreads();
    }
    mx = red[0]; __syncthreads();
    float sum = 0.f;
#pragma unroll
    for (int r = 0; r < 4; r++) { v[r] = __expf(v[r] - mx); sum += v[r]; }
    red[tid] = sum; __syncthreads();
    for (int st = 128; st > 0; st >>= 1) {
        if (tid < st) red[tid] += red[tid + st];
        __syncthreads();
    }
    const float inv = 1.f / red[0];
#pragma unroll
    for (int r = 0; r < 4; r++) p[tid + r * 256] = v[r] * inv;
}

// ---------------- LayerNorm over D=512 ----------------
__global__ void __launch_bounds__(256)
layernorm_kernel(const float* __restrict__ x, const float* __restrict__ gamma,
                 const float* __restrict__ beta, float* __restrict__ out, int D)
{
    const int row = blockIdx.x;
    const float* p = x + (long)row * D;
    const int tid = threadIdx.x;
    const float a0 = p[tid];
    const float a1 = p[tid + 256];
    __shared__ float red[256];
    red[tid] = a0 + a1; __syncthreads();
    for (int st = 128; st > 0; st >>= 1) {
        if (tid < st) red[tid] += red[tid + st];
        __syncthreads();
    }
    const float mean = red[0] / (float)D; __syncthreads();
    const float d0 = a0 - mean, d1 = a1 - mean;
    red[tid] = d0 * d0 + d1 * d1; __syncthreads();
    for (int st = 128; st > 0; st >>= 1) {
        if (tid < st) red[tid] += red[tid + st];
        __syncthreads();
    }
    const float rstd = rsqrtf(red[0] / (float)D + 1e-5f);
    out[(long)row * D + tid]       = d0 * rstd * gamma[tid] + beta[tid];
    out[(long)row * D + tid + 256] = d1 * rstd * gamma[tid + 256] + beta[tid + 256];
}

// ---------------- launch ----------------
extern "C" void kernel_launch(void* const* d_in, const int* in_sizes, int n_in,
                              void* d_out, int out_size)
{
    const float* Q     = (const float*)d_in[0];
    const float* Kin   = (const float*)d_in[1];
    const float* Vin   = (const float*)d_in[2];
    const void*  Mask  = d_in[3];
    const float* Wq    = (const float*)d_in[4];
    const float* bq    = (const float*)d_in[5];
    const float* Wk    = (const float*)d_in[6];
    const float* bv    = (const float*)d_in[9];
    const float* Wv    = (const float*)d_in[8];
    const float* Wo    = (const float*)d_in[10];
    const float* bo    = (const float*)d_in[11];
    const float* gamma = (const float*)d_in[12];
    const float* beta  = (const float*)d_in[13];
    float* out = (float*)d_out;

    float *qm, *s, *ctxv, *vt, *wot, *mt, *nt, *o, *vv, *w2, *cpart, *crow;
    cudaGetSymbolAddress((void**)&qm,   g_qm);
    cudaGetSymbolAddress((void**)&s,    g_s);
    cudaGetSymbolAddress((void**)&ctxv, g_ctxv);
    cudaGetSymbolAddress((void**)&vt,   g_vt);
    cudaGetSymbolAddress((void**)&wot,  g_wot);
    cudaGetSymbolAddress((void**)&mt,   g_mt);
    cudaGetSymbolAddress((void**)&nt,   g_nt);
    cudaGetSymbolAddress((void**)&o,    g_o);
    cudaGetSymbolAddress((void**)&vv,   g_vv);
    cudaGetSymbolAddress((void**)&w2,   g_w2);
    cudaGetSymbolAddress((void**)&cpart, g_cpart);
    cudaGetSymbolAddress((void**)&crow, g_crow);

    cudaFuncSetAttribute(tc_gemm, cudaFuncAttributeMaxDynamicSharedMemorySize, GEMM_SMEM);

    const int S = 1024, H = 8;
    const long SS = (long)S * S;
    dim3 blk(256);

    // launches 0-4: mask dtype, transposes, w2, vv  (launch 5 = G1 for ncu -s 5)
    detect_mask_kernel<<<1, 256>>>((const unsigned int*)Mask);
    transpose_kernel<<<dim3(16, 256, 1), dim3(32, 8)>>>(Wo, wot, 8192, 512, 0, 0);
    transpose_kernel<<<dim3(16, 32, 8), dim3(32, 8)>>>(Vin, vt, 1024, 512,
                                                       524288, 524288);
    w2_kernel<<<dim3(512, 8), blk>>>(Wk, bq, w2);
    vv_kernel<<<8192, blk>>>(Kin, w2, vv, 0.03125f);

    // G1 (launch 5): mt[h][q][p] = sum_d Wk[q,h*1024+d] * Wq[p,h*1024+d]
    tc_gemm<<<dim3(4, 4, 8), blk, GEMM_SMEM>>>(Wk, Wq, nullptr, nullptr, mt,
        1024, 8192, 8192, 512,
        0, 1024, 0, 1024, 0, (long)512 * 512, 8);

    // G2: qm[h][i][q] = (Q @ M_h)[i,q]
    tc_gemm<<<dim3(4, 64, 8), blk, GEMM_SMEM>>>(Q, mt, nullptr, nullptr, qm,
        512, 512, 512, 512,
        0, 0, 0, (long)512 * 512, 0, (long)8192 * 512, 8);

    // G3: s[b][h][i][j] = sum_q qm[h][b*1024+i][q] * K[b*1024+j][q]
    tc_gemm<<<dim3(8, 8, 64), blk, GEMM_SMEM>>>(qm, Kin, nullptr, nullptr, s,
        512, 512, 512, 1024,
        (long)1024 * 512, (long)8192 * 512,
        (long)1024 * 512, 0,
        (long)H * SS, SS, 8);

    // softmax with column bias (scale = 1/sqrt(dh) = 1/32)
    softmax_kernel<<<dim3(S, 64), blk>>>(s, Mask, vv, S, H, 0.03125f);

    // G5: ctxv[b*1024+i][h*512+p] = sum_j attn[b,h][i,j] * vt[b][p][j]
    tc_gemm<<<dim3(4, 8, 64), blk, GEMM_SMEM>>>(s, vt, nullptr, nullptr, ctxv,
        1024, 1024, 1024, 4096,
        (long)H * SS, SS,
        (long)512 * 1024, 0,
        (long)1024 * 4096, 512, 8);

    // G6: nt[o][h*512+p] = sum_d wot[o,h*1024+d] * Wv[p,h*1024+d]
    tc_gemm<<<dim3(4, 4, 8), blk, GEMM_SMEM>>>(wot, Wv, nullptr, nullptr, nt,
        1024, 8192, 8192, 4096,
        0, 1024, 0, 1024, 0, 512, 8);

    // crow (needed only by G7)
    crowA_kernel<<<128, blk>>>(Wo, bv, cpart);
    crowB_kernel<<<1, 512>>>(cpart, bo, crow);

    // G7: o[i][o'] = sum_{hp} ctxv[i][hp] * nt[o'][hp] + crow[o'] + Q[i][o']
    tc_gemm<<<dim3(4, 64, 1), blk, GEMM_SMEM>>>(ctxv, nt, crow, Q, o,
        4096, 4096, 4096, 512,
        0, 0, 0, 0, 0, 0, 1);

    // LayerNorm
    layernorm_kernel<<<8192, blk>>>(o, gamma, beta, out, 512);
}

// round 12
// speedup vs baseline: 5.7340x; 1.3558x over previous
#include <cuda_runtime.h>
#include <cuda_bf16.h>
#include <cstdint>

// ============================================================================
// MultiHeadAttention, reassociated weights + pre-split bf16 cp.async GEMM.
// B=8, S=1024, D=512, H=8, DH=1024.
//
// Algebra: q.k^T = Q (Wq_h Wk_h^T) K^T ; ctx@Wo = sum_h (attn_h @ V)(Wv_h Wo_h).
// Round 12: all GEMM operands live in gmem as PRE-SPLIT bf16 hi/lo pairs
// (x = hi + lo, 3-product accumulation unchanged). GEMM loads them with
// cp.async directly into swizzled smem -- no fp32->bf16 conversion in the hot
// loop. GEMM epilogues emit split bf16 for downstream GEMMs; softmax emits
// split attn; G7 emits fp32 for LayerNorm. MMA/ldmatrix block identical to
// the round-11 passing kernel.
// ============================================================================

#define LDSM_X4(r0, r1, r2, r3, addr) \
    asm volatile("ldmatrix.sync.aligned.m8n8.x4.shared.b16 {%0,%1,%2,%3}, [%4];" \
                 : "=r"(r0), "=r"(r1), "=r"(r2), "=r"(r3) : "r"(addr))

#define MMA_BF16(d, a, b0, b1) \
    asm volatile("mma.sync.aligned.m16n8k16.row.col.f32.bf16.bf16.f32 " \
                 "{%0,%1,%2,%3}, {%4,%5,%6,%7}, {%8,%9}, {%0,%1,%2,%3};" \
                 : "+f"((d)[0]), "+f"((d)[1]), "+f"((d)[2]), "+f"((d)[3]) \
                 : "r"((a)[0]), "r"((a)[1]), "r"((a)[2]), "r"((a)[3]), \
                   "r"(b0), "r"(b1))

#define CP_ASYNC16(saddr, gptr) \
    asm volatile("cp.async.cg.shared.global [%0], [%1], 16;" \
                 :: "r"(saddr), "l"(gptr) : "memory")
#define CP_COMMIT() asm volatile("cp.async.commit_group;" ::: "memory")
#define CP_WAIT1()  asm volatile("cp.async.wait_group 1;" ::: "memory")
#define CP_WAIT0()  asm volatile("cp.async.wait_group 0;" ::: "memory")

__device__ __forceinline__ uint32_t smem_u32(const void* p) {
    uint32_t a;
    asm("{ .reg .u64 t; cvta.to.shared.u64 t, %1; cvt.u32.u64 %0, t; }"
        : "=r"(a) : "l"(p));
    return a;
}
// pack hi parts (top 16 bits) of two floats -> bf16x2 (x low)
__device__ __forceinline__ uint32_t pack_hi(float x, float y) {
    uint32_t r;
    asm("prmt.b32 %0, %1, %2, 0x7632;"
        : "=r"(r) : "r"(__float_as_uint(x)), "r"(__float_as_uint(y)));
    return r;
}
// rn-convert two floats to bf16x2 (x low half)
__device__ __forceinline__ uint32_t pack_rn(float x, float y) {
    uint32_t r;
    asm("cvt.rn.bf16x2.f32 %0, %1, %2;" : "=r"(r) : "f"(y), "f"(x));
    return r;
}
__device__ __forceinline__ unsigned short bf16_rn(float x) {
    unsigned short r;
    asm("cvt.rn.bf16.f32 %0, %1;" : "=h"(r) : "f"(x));
    return r;
}

// ---------------- device scratch ----------------
// split bf16 pairs (unsigned short = raw bf16 bits)
__device__ __align__(256) unsigned short g_wkh[(size_t)512 * 8192],  g_wkl[(size_t)512 * 8192];
__device__ __align__(256) unsigned short g_wqh[(size_t)512 * 8192],  g_wql[(size_t)512 * 8192];
__device__ __align__(256) unsigned short g_wvh[(size_t)512 * 8192],  g_wvl[(size_t)512 * 8192];
__device__ __align__(256) unsigned short g_qh [(size_t)8192 * 512],  g_ql [(size_t)8192 * 512];
__device__ __align__(256) unsigned short g_kh [(size_t)8192 * 512],  g_kl [(size_t)8192 * 512];
__device__ __align__(256) unsigned short g_woth[(size_t)512 * 8192], g_wotl[(size_t)512 * 8192];
__device__ __align__(256) unsigned short g_vth[(size_t)8 * 512 * 1024], g_vtl[(size_t)8 * 512 * 1024];
__device__ __align__(256) unsigned short g_mth[(size_t)8 * 512 * 512],  g_mtl[(size_t)8 * 512 * 512];
__device__ __align__(256) unsigned short g_qmh[(size_t)8 * 8192 * 512], g_qml[(size_t)8 * 8192 * 512];
__device__ __align__(256) unsigned short g_ah [(size_t)64 * 1024 * 1024], g_al [(size_t)64 * 1024 * 1024];
__device__ __align__(256) unsigned short g_cvh[(size_t)8192 * 4096], g_cvl[(size_t)8192 * 4096];
__device__ __align__(256) unsigned short g_nth[(size_t)512 * 4096],  g_ntl[(size_t)512 * 4096];
// fp32
__device__ __align__(256) float g_s   [(size_t)64 * 1024 * 1024]; // scores fp32
__device__ __align__(256) float g_o   [(size_t)8192 * 512];       // pre-LN
__device__ __align__(256) float g_vv  [8 * 8192];
__device__ __align__(256) float g_w2  [8 * 512];
__device__ __align__(256) float g_cpart[128 * 512];
__device__ __align__(256) float g_crow[512];
__device__ int g_mask_mode;

// ---------------- mask dtype detection ----------------
__global__ void detect_mask_kernel(const unsigned int* __restrict__ m) {
    __shared__ int sawFloat, sawByte;
    if (threadIdx.x == 0) { sawFloat = 0; sawByte = 0; }
    __syncthreads();
    for (int i = threadIdx.x; i < 4096; i += 256) {
        unsigned int w = m[i];
        if (w == 0x3F800000u) sawFloat = 1;
        else if (w > 1u) sawByte = 1;
    }
    __syncthreads();
    if (threadIdx.x == 0) g_mask_mode = sawFloat ? 2 : (sawByte ? 0 : 1);
}

// ---------------- fp32 -> (hi,lo) bf16 split, elementwise ----------------
__global__ void __launch_bounds__(256)
split_kernel(const float* __restrict__ in, unsigned short* __restrict__ hi,
             unsigned short* __restrict__ lo, long n4) {
    long i = (long)blockIdx.x * 256 + threadIdx.x;
    const long stride = (long)gridDim.x * 256;
    for (; i < n4; i += stride) {
        float4 x = ((const float4*)in)[i];
        float t0 = __uint_as_float(__float_as_uint(x.x) & 0xFFFF0000u);
        float t1 = __uint_as_float(__float_as_uint(x.y) & 0xFFFF0000u);
        float t2 = __uint_as_float(__float_as_uint(x.z) & 0xFFFF0000u);
        float t3 = __uint_as_float(__float_as_uint(x.w) & 0xFFFF0000u);
        uint2 hp = { pack_hi(x.x, x.y), pack_hi(x.z, x.w) };
        uint2 lp = { pack_rn(x.x - t0, x.y - t1), pack_rn(x.z - t2, x.w - t3) };
        ((uint2*)hi)[i] = hp;
        ((uint2*)lo)[i] = lp;
    }
}

// ---------------- transpose [R,C] -> [C,R] with split output ----------------
__global__ void __launch_bounds__(256)
transpose_split_kernel(const float* __restrict__ in,
                       unsigned short* __restrict__ hi,
                       unsigned short* __restrict__ lo,
                       int R, int C, long inO, long outO) {
    in += (long)blockIdx.z * inO;
    hi += (long)blockIdx.z * outO;
    lo += (long)blockIdx.z * outO;
    __shared__ float t[32][33];
    int x = blockIdx.x * 32 + threadIdx.x;
    int y0 = blockIdx.y * 32;
#pragma unroll
    for (int j = threadIdx.y; j < 32; j += 8)
        t[j][threadIdx.x] = in[(long)(y0 + j) * C + x];
    __syncthreads();
    int xo = blockIdx.y * 32 + threadIdx.x;
    int yo0 = blockIdx.x * 32;
#pragma unroll
    for (int j = threadIdx.y; j < 32; j += 8) {
        float v = t[threadIdx.x][j];
        uint32_t u = __float_as_uint(v);
        long idx = (long)(yo0 + j) * R + xo;
        hi[idx] = (unsigned short)(u >> 16);
        lo[idx] = bf16_rn(v - __uint_as_float(u & 0xFFFF0000u));
    }
}

// ---------------- bias helper kernels ----------------
__global__ void __launch_bounds__(256)
w2_kernel(const float* __restrict__ Wk, const float* __restrict__ bq,
          float* __restrict__ w2) {
    const int p = blockIdx.x, h = blockIdx.y;
    const int tid = threadIdx.x;
    const float4 a = *(const float4*)(Wk + (long)p * 8192 + h * 1024 + tid * 4);
    const float4 b = *(const float4*)(bq + h * 1024 + tid * 4);
    float s = a.x * b.x + a.y * b.y + a.z * b.z + a.w * b.w;
    __shared__ float red[256];
    red[tid] = s; __syncthreads();
    for (int st = 128; st > 0; st >>= 1) {
        if (tid < st) red[tid] += red[tid + st];
        __syncthreads();
    }
    if (tid == 0) w2[h * 512 + p] = red[0];
}
__global__ void __launch_bounds__(256)
vv_kernel(const float* __restrict__ K, const float* __restrict__ w2,
          float* __restrict__ vv, float scale) {
    const int j = blockIdx.x;
    const int tid = threadIdx.x;
    const int wid = tid >> 5, lane = tid & 31;
    __shared__ float kr[512];
    for (int i = tid; i < 512; i += 256) kr[i] = K[(long)j * 512 + i];
    __syncthreads();
    const float* wr = w2 + wid * 512;
    float s = 0.f;
    for (int p = lane; p < 512; p += 32) s += kr[p] * wr[p];
#pragma unroll
    for (int o = 16; o > 0; o >>= 1) s += __shfl_down_sync(0xFFFFFFFFu, s, o);
    if (lane == 0) vv[wid * 8192 + j] = s * scale;
}
__global__ void __launch_bounds__(256)
crowA_kernel(const float* __restrict__ Wo, const float* __restrict__ bvv,
             float* __restrict__ cpart) {
    const int m0 = blockIdx.x * 64;
    const int tid = threadIdx.x;
    __shared__ float bvs[64];
    if (tid < 64) bvs[tid] = bvv[m0 + tid];
    __syncthreads();
    float s0 = 0.f, s1 = 0.f;
    for (int m = 0; m < 64; m++) {
        const float b = bvs[m];
        const float* row = Wo + (long)(m0 + m) * 512;
        s0 += b * row[tid];
        s1 += b * row[tid + 256];
    }
    cpart[blockIdx.x * 512 + tid] = s0;
    cpart[blockIdx.x * 512 + tid + 256] = s1;
}
__global__ void crowB_kernel(const float* __restrict__ cpart,
                             const float* __restrict__ bo, float* __restrict__ crow) {
    const int o = threadIdx.x;
    float s = bo[o];
    for (int b = 0; b < 128; b++) s += cpart[b * 512 + o];
    crow[o] = s;
}

// ============================================================================
// Pre-split bf16 GEMM: C = A @ B^T; A,B given as hi/lo bf16 K-major arrays.
// 128x128 tile, BK=32, 256 threads (8 warps of 64x32), cp.async double buffer.
// Output: fp32 C (+bias +res) when Ch==nullptr, else split bf16 (Ch,Cl).
// ============================================================================
#define OFF_A_HI 0
#define OFF_A_LO 8192
#define OFF_B_HI 16384
#define OFF_B_LO 24576
#define STAGE 32768
#define GEMM_SMEM (2 * STAGE)

__global__ void __launch_bounds__(256)
tc_gemm2(const unsigned short* __restrict__ Ah, const unsigned short* __restrict__ Al,
         const unsigned short* __restrict__ Bh, const unsigned short* __restrict__ Bl,
         const float* __restrict__ bias, const float* __restrict__ res,
         float* __restrict__ C, unsigned short* __restrict__ Ch,
         unsigned short* __restrict__ Cl,
         int K, int lda, int ldb, int ldc,
         long aO1, long aO2, long bO1, long bO2, long cO1, long cO2, int HD)
{
    extern __shared__ char smem[];
    const uint32_t sb = smem_u32(smem);
    const int tid = threadIdx.x;
    const int wid = tid >> 5;
    const int lane = tid & 31;

    const int z = blockIdx.z;
    const int zb = z / HD, zh = z % HD;
    const long aOff = (long)zb * aO1 + (long)zh * aO2;
    const long bOff = (long)zb * bO1 + (long)zh * bO2;
    const long cOff = (long)zb * cO1 + (long)zh * cO2;

    const int row0 = blockIdx.y * 128;
    const int col0 = blockIdx.x * 128;

    const int wr = wid >> 2;
    const int wc = wid & 3;
    const int wm = wr * 64;
    const int wn = wc * 32;

    // ---- cp.async loader map: thread t -> row t>>1, chunk pair (t&1)*2 ----
    const int lrow = tid >> 1;                 // 0..127
    const int c0 = (tid & 1) * 2;              // chunk 0 or 2
    const uint32_t srow = lrow * 64;
    const uint32_t sw0 = (uint32_t)((c0 ^ (lrow & 3)) << 4);
    const uint32_t sw1 = (uint32_t)(((c0 + 1) ^ (lrow & 3)) << 4);
    const unsigned short* gAh = Ah + aOff + (long)(row0 + lrow) * lda + c0 * 8;
    const unsigned short* gAl = Al + aOff + (long)(row0 + lrow) * lda + c0 * 8;
    const unsigned short* gBh = Bh + bOff + (long)(col0 + lrow) * ldb + c0 * 8;
    const unsigned short* gBl = Bl + bOff + (long)(col0 + lrow) * ldb + c0 * 8;

    // ---- ldmatrix per-thread address components (identical to prior kernel) --
    const int a_rowoff = ((lane >> 3) & 1) * 8 + (lane & 7);
    const int a_ksel = lane >> 4;
    const int a_swz = a_rowoff & 3;
    const int b_rowoff = (lane >> 4) * 8 + (lane & 7);
    const int b_ksel = (lane >> 3) & 1;
    const int b_swz = b_rowoff & 3;

    float acc[4][4][4];
#pragma unroll
    for (int mi = 0; mi < 4; mi++)
#pragma unroll
        for (int ni = 0; ni < 4; ni++)
#pragma unroll
            for (int e = 0; e < 4; e++) acc[mi][ni][e] = 0.f;

    const int nch = K >> 5;

    // prologue: chunk 0 -> buffer 0
    {
        const uint32_t st = sb;
        CP_ASYNC16(st + OFF_A_HI + srow + sw0, gAh);
        CP_ASYNC16(st + OFF_A_HI + srow + sw1, gAh + 8);
        CP_ASYNC16(st + OFF_A_LO + srow + sw0, gAl);
        CP_ASYNC16(st + OFF_A_LO + srow + sw1, gAl + 8);
        CP_ASYNC16(st + OFF_B_HI + srow + sw0, gBh);
        CP_ASYNC16(st + OFF_B_HI + srow + sw1, gBh + 8);
        CP_ASYNC16(st + OFF_B_LO + srow + sw0, gBl);
        CP_ASYNC16(st + OFF_B_LO + srow + sw1, gBl + 8);
        CP_COMMIT();
    }

    for (int ch = 0; ch < nch; ch++) {
        const int buf = ch & 1;
        const uint32_t stb = sb + buf * STAGE;
        const bool more = (ch + 1) < nch;

        if (more) {
            const int kt = (ch + 1) << 5;
            const uint32_t st = sb + (buf ^ 1) * STAGE;
            CP_ASYNC16(st + OFF_A_HI + srow + sw0, gAh + kt);
            CP_ASYNC16(st + OFF_A_HI + srow + sw1, gAh + kt + 8);
            CP_ASYNC16(st + OFF_A_LO + srow + sw0, gAl + kt);
            CP_ASYNC16(st + OFF_A_LO + srow + sw1, gAl + kt + 8);
            CP_ASYNC16(st + OFF_B_HI + srow + sw0, gBh + kt);
            CP_ASYNC16(st + OFF_B_HI + srow + sw1, gBh + kt + 8);
            CP_ASYNC16(st + OFF_B_LO + srow + sw0, gBl + kt);
            CP_ASYNC16(st + OFF_B_LO + srow + sw1, gBl + kt + 8);
            CP_COMMIT();
            CP_WAIT1();
        } else {
            CP_WAIT0();
        }
        __syncthreads();

        // ---- MMA over current stage (identical structure) ----
        const uint32_t aBaseHi = stb + OFF_A_HI + (wm + a_rowoff) * 64;
        const uint32_t aBaseLo = stb + OFF_A_LO + (wm + a_rowoff) * 64;
#pragma unroll
        for (int ks = 0; ks < 2; ks++) {
            uint32_t bh[8], bl[8];
            {
                const uint32_t csel = ((uint32_t)(ks * 2 + b_ksel) ^ b_swz) << 4;
#pragma unroll
                for (int p = 0; p < 2; p++) {
                    const uint32_t ro = (wn + p * 16 + b_rowoff) * 64 + csel;
                    LDSM_X4(bh[p*4+0], bh[p*4+1], bh[p*4+2], bh[p*4+3],
                            stb + OFF_B_HI + ro);
                    LDSM_X4(bl[p*4+0], bl[p*4+1], bl[p*4+2], bl[p*4+3],
                            stb + OFF_B_LO + ro);
                }
            }
            const uint32_t acsel = ((uint32_t)(ks * 2 + a_ksel) ^ a_swz) << 4;
#pragma unroll
            for (int mi = 0; mi < 4; mi++) {
                uint32_t ah[4], al[4];
                LDSM_X4(ah[0], ah[1], ah[2], ah[3], aBaseHi + mi * 16 * 64 + acsel);
                LDSM_X4(al[0], al[1], al[2], al[3], aBaseLo + mi * 16 * 64 + acsel);
#pragma unroll
                for (int ni = 0; ni < 4; ni++)
                    MMA_BF16(acc[mi][ni], ah, bh[ni*2], bh[ni*2+1]);
#pragma unroll
                for (int ni = 0; ni < 4; ni++)
                    MMA_BF16(acc[mi][ni], ah, bl[ni*2], bl[ni*2+1]);
#pragma unroll
                for (int ni = 0; ni < 4; ni++)
                    MMA_BF16(acc[mi][ni], al, bh[ni*2], bh[ni*2+1]);
            }
        }
        __syncthreads();
    }

    // ---- epilogue ----
    const int erow = lane >> 2;
    const int ecol = (lane & 3) * 2;
#pragma unroll
    for (int mi = 0; mi < 4; mi++) {
        const int r0 = row0 + wm + mi * 16 + erow;
        const int r1 = r0 + 8;
#pragma unroll
        for (int ni = 0; ni < 4; ni++) {
            const int c = col0 + wn + ni * 8 + ecol;
            float v0 = acc[mi][ni][0], v1 = acc[mi][ni][1];
            float v2 = acc[mi][ni][2], v3 = acc[mi][ni][3];
            if (bias) {
                const float b0 = bias[c], b1 = bias[c + 1];
                v0 += b0; v1 += b1; v2 += b0; v3 += b1;
            }
            if (res) {
                float2 q0 = *(const float2*)(res + (long)r0 * ldc + c);
                float2 q1 = *(const float2*)(res + (long)r1 * ldc + c);
                v0 += q0.x; v1 += q0.y; v2 += q1.x; v3 += q1.y;
            }
            if (Ch) {
                float t0 = __uint_as_float(__float_as_uint(v0) & 0xFFFF0000u);
                float t1 = __uint_as_float(__float_as_uint(v1) & 0xFFFF0000u);
                float t2 = __uint_as_float(__float_as_uint(v2) & 0xFFFF0000u);
                float t3 = __uint_as_float(__float_as_uint(v3) & 0xFFFF0000u);
                *(uint32_t*)(Ch + cOff + (long)r0 * ldc + c) = pack_hi(v0, v1);
                *(uint32_t*)(Cl + cOff + (long)r0 * ldc + c) = pack_rn(v0 - t0, v1 - t1);
                *(uint32_t*)(Ch + cOff + (long)r1 * ldc + c) = pack_hi(v2, v3);
                *(uint32_t*)(Cl + cOff + (long)r1 * ldc + c) = pack_rn(v2 - t2, v3 - t3);
            } else {
                float2 o0 = {v0, v1}, o1 = {v2, v3};
                *(float2*)(C + cOff + (long)r0 * ldc + c) = o0;
                *(float2*)(C + cOff + (long)r1 * ldc + c) = o1;
            }
        }
    }
}

// ---------------- softmax: fp32 scores -> split bf16 attn ----------------
__global__ void __launch_bounds__(256)
softmax_kernel(const float* __restrict__ s, const void* __restrict__ mask,
               const float* __restrict__ vv,
               unsigned short* __restrict__ ah, unsigned short* __restrict__ al,
               int S, int H, float scale)
{
    const int i = blockIdx.x;
    const int z = blockIdx.y;
    const int b = z / H;
    const int h = z % H;
    const long base = ((long)z * S + (long)i) * S;
    const float* p = s + base;
    const float* vsp = vv + h * 8192 + b * 1024;
    const long mbase = (long)b * S * S + (long)i * S;
    const int tid = threadIdx.x;
    const int mode = g_mask_mode;

    bool mk[4];
    if (mode == 0) {
        const unsigned char* mp = (const unsigned char*)mask + mbase;
#pragma unroll
        for (int r = 0; r < 4; r++) mk[r] = mp[tid + r * 256] != 0;
    } else if (mode == 1) {
        const int* mp = (const int*)mask + mbase;
#pragma unroll
        for (int r = 0; r < 4; r++) mk[r] = mp[tid + r * 256] != 0;
    } else {
        const float* mp = (const float*)mask + mbase;
#pragma unroll
        for (int r = 0; r < 4; r++) mk[r] = mp[tid + r * 256] != 0.f;
    }

    float v[4];
    float mx = -3.4e38f;
#pragma unroll
    for (int r = 0; r < 4; r++) {
        const int j = tid + r * 256;
        float x = p[j] * scale + vsp[j];
        if (mk[r]) x = -1e9f;
        v[r] = x;
        mx = fmaxf(mx, x);
    }
    __shared__ float red[256];
    red[tid] = mx; __syncthreads();
    for (int st = 128; st > 0; st >>= 1) {
        if (tid < st) red[tid] = fmaxf(red[tid], red[tid + st]);
        __syncthreads();
    }
    mx = red[0]; __syncthreads();
    float sum = 0.f;
#pragma unroll
    for (int r = 0; r < 4; r++) { v[r] = __expf(v[r] - mx); sum += v[r]; }
    red[tid] = sum; __syncthreads();
    for (int st = 128; st > 0; st >>= 1) {
        if (tid < st) red[tid] += red[tid + st];
        __syncthreads();
    }
    const float inv = 1.f / red[0];
#pragma unroll
    for (int r = 0; r < 4; r++) {
        const long idx = base + tid + r * 256;
        const float x = v[r] * inv;
        const uint32_t u = __float_as_uint(x);
        ah[idx] = (unsigned short)(u >> 16);
        al[idx] = bf16_rn(x - __uint_as_float(u & 0xFFFF0000u));
    }
}

// ---------------- LayerNorm over D=512 ----------------
__global__ void __launch_bounds__(256)
layernorm_kernel(const float* __restrict__ x, const float* __restrict__ gamma,
                 const float* __restrict__ beta, float* __restrict__ out, int D)
{
    const int row = blockIdx.x;
    const float* p = x + (long)row * D;
    const int tid = threadIdx.x;
    const float a0 = p[tid];
    const float a1 = p[tid + 256];
    __shared__ float red[256];
    red[tid] = a0 + a1; __syncthreads();
    for (int st = 128; st > 0; st >>= 1) {
        if (tid < st) red[tid] += red[tid + st];
        __syncthreads();
    }
    const float mean = red[0] / (float)D; __syncthreads();
    const float d0 = a0 - mean, d1 = a1 - mean;
    red[tid] = d0 * d0 + d1 * d1; __syncthreads();
    for (int st = 128; st > 0; st >>= 1) {
        if (tid < st) red[tid] += red[tid + st];
        __syncthreads();
    }
    const float rstd = rsqrtf(red[0] / (float)D + 1e-5f);
    out[(long)row * D + tid]       = d0 * rstd * gamma[tid] + beta[tid];
    out[(long)row * D + tid + 256] = d1 * rstd * gamma[tid + 256] + beta[tid + 256];
}

// ---------------- launch ----------------
extern "C" void kernel_launch(void* const* d_in, const int* in_sizes, int n_in,
                              void* d_out, int out_size)
{
    const float* Q     = (const float*)d_in[0];
    const float* Kin   = (const float*)d_in[1];
    const float* Vin   = (const float*)d_in[2];
    const void*  Mask  = d_in[3];
    const float* Wq    = (const float*)d_in[4];
    const float* bq    = (const float*)d_in[5];
    const float* Wk    = (const float*)d_in[6];
    const float* bv    = (const float*)d_in[9];
    const float* Wv    = (const float*)d_in[8];
    const float* Wo    = (const float*)d_in[10];
    const float* bo    = (const float*)d_in[11];
    const float* gamma = (const float*)d_in[12];
    const float* beta  = (const float*)d_in[13];
    float* out = (float*)d_out;

    unsigned short *wkh,*wkl,*wqh,*wql,*wvh,*wvl,*qh,*ql,*kh,*kl;
    unsigned short *woth,*wotl,*vth,*vtl,*mth,*mtl,*qmh,*qml,*ah,*al,*cvh,*cvl,*nth,*ntl;
    float *s,*o,*vv,*w2,*cpart,*crow;
    cudaGetSymbolAddress((void**)&wkh, g_wkh);  cudaGetSymbolAddress((void**)&wkl, g_wkl);
    cudaGetSymbolAddress((void**)&wqh, g_wqh);  cudaGetSymbolAddress((void**)&wql, g_wql);
    cudaGetSymbolAddress((void**)&wvh, g_wvh);  cudaGetSymbolAddress((void**)&wvl, g_wvl);
    cudaGetSymbolAddress((void**)&qh,  g_qh);   cudaGetSymbolAddress((void**)&ql,  g_ql);
    cudaGetSymbolAddress((void**)&kh,  g_kh);   cudaGetSymbolAddress((void**)&kl,  g_kl);
    cudaGetSymbolAddress((void**)&woth,g_woth); cudaGetSymbolAddress((void**)&wotl,g_wotl);
    cudaGetSymbolAddress((void**)&vth, g_vth);  cudaGetSymbolAddress((void**)&vtl, g_vtl);
    cudaGetSymbolAddress((void**)&mth, g_mth);  cudaGetSymbolAddress((void**)&mtl, g_mtl);
    cudaGetSymbolAddress((void**)&qmh, g_qmh);  cudaGetSymbolAddress((void**)&qml, g_qml);
    cudaGetSymbolAddress((void**)&ah,  g_ah);   cudaGetSymbolAddress((void**)&al,  g_al);
    cudaGetSymbolAddress((void**)&cvh, g_cvh);  cudaGetSymbolAddress((void**)&cvl, g_cvl);
    cudaGetSymbolAddress((void**)&nth, g_nth);  cudaGetSymbolAddress((void**)&ntl, g_ntl);
    cudaGetSymbolAddress((void**)&s,   g_s);
    cudaGetSymbolAddress((void**)&o,   g_o);
    cudaGetSymbolAddress((void**)&vv,  g_vv);
    cudaGetSymbolAddress((void**)&w2,  g_w2);
    cudaGetSymbolAddress((void**)&cpart, g_cpart);
    cudaGetSymbolAddress((void**)&crow,  g_crow);

    cudaFuncSetAttribute(tc_gemm2, cudaFuncAttributeMaxDynamicSharedMemorySize, GEMM_SMEM);

    const int S = 1024, H = 8;
    const long SS = (long)S * S;
    const long N4W = (long)512 * 8192 / 4;   // weight-sized arrays / float4
    dim3 blk(256);

    // 0-4: mask dtype + splits feeding G1..G3
    detect_mask_kernel<<<1, 256>>>((const unsigned int*)Mask);
    split_kernel<<<1024, blk>>>(Wk,  wkh, wkl, N4W);
    split_kernel<<<1024, blk>>>(Wq,  wqh, wql, N4W);
    split_kernel<<<1024, blk>>>(Q,   qh,  ql,  N4W);
    split_kernel<<<1024, blk>>>(Kin, kh,  kl,  N4W);

    // G1 (launch 5): mt[h][q][p] = sum_d Wk[q,hd] * Wq[p,hd]
    tc_gemm2<<<dim3(4, 4, 8), blk, GEMM_SMEM>>>(wkh, wkl, wqh, wql,
        nullptr, nullptr, nullptr, mth, mtl,
        1024, 8192, 8192, 512,
        0, 1024, 0, 1024, 0, (long)512 * 512, 8);

    // G2: qm[h][i][q] = (Q @ M_h)[i,q]
    tc_gemm2<<<dim3(4, 64, 8), blk, GEMM_SMEM>>>(qh, ql, mth, mtl,
        nullptr, nullptr, nullptr, qmh, qml,
        512, 512, 512, 512,
        0, 0, 0, (long)512 * 512, 0, (long)8192 * 512, 8);

    // G3: s (fp32) = qm @ K^T per (b,h)
    tc_gemm2<<<dim3(8, 8, 64), blk, GEMM_SMEM>>>(qmh, qml, kh, kl,
        nullptr, nullptr, s, nullptr, nullptr,
        512, 512, 512, 1024,
        (long)1024 * 512, (long)8192 * 512,
        (long)1024 * 512, 0,
        (long)H * SS, SS, 8);

    // helpers + remaining splits (overlap window before softmax/G5/G6)
    w2_kernel<<<dim3(512, 8), blk>>>(Wk, bq, w2);
    vv_kernel<<<8192, blk>>>(Kin, w2, vv, 0.03125f);
    split_kernel<<<1024, blk>>>(Wv, wvh, wvl, N4W);
    transpose_split_kernel<<<dim3(16, 256, 1), dim3(32, 8)>>>(Wo, woth, wotl,
                                                              8192, 512, 0, 0);
    transpose_split_kernel<<<dim3(16, 32, 8), dim3(32, 8)>>>(Vin, vth, vtl,
                                                             1024, 512, 524288, 524288);

    // softmax: scale + col-bias + mask + softmax -> split bf16 attn
    softmax_kernel<<<dim3(S, 64), blk>>>(s, Mask, vv, ah, al, S, H, 0.03125f);

    // G5: ctxv[b*1024+i][h*512+p] = attn @ vt^T  -> split
    tc_gemm2<<<dim3(4, 8, 64), blk, GEMM_SMEM>>>(ah, al, vth, vtl,
        nullptr, nullptr, nullptr, cvh, cvl,
        1024, 1024, 1024, 4096,
        (long)H * SS, SS,
        (long)512 * 1024, 0,
        (long)1024 * 4096, 512, 8);

    // G6: nt[o][h*512+p] = wot @ Wv^T per h -> split
    tc_gemm2<<<dim3(4, 4, 8), blk, GEMM_SMEM>>>(woth, wotl, wvh, wvl,
        nullptr, nullptr, nullptr, nth, ntl,
        1024, 8192, 8192, 4096,
        0, 1024, 0, 1024, 0, 512, 8);

    // crow (needed only by G7)
    crowA_kernel<<<128, blk>>>(Wo, bv, cpart);
    crowB_kernel<<<1, 512>>>(cpart, bo, crow);

    // G7: o = ctxv @ nt^T + crow + Q  (fp32 out)
    tc_gemm2<<<dim3(4, 64, 1), blk, GEMM_SMEM>>>(cvh, cvl, nth, ntl,
        crow, Q, o, nullptr, nullptr,
        4096, 4096, 4096, 512,
        0, 0, 0, 0, 0, 0, 1);

    // LayerNorm
    layernorm_kernel<<<8192, blk>>>(o, gamma, beta, out, 512);
}